// round 1
// baseline (speedup 1.0000x reference)
#include <cuda_runtime.h>
#include <math.h>

// ---------------- problem constants ----------------
#define N_NODES   20000
#define N_EDGES   320000
#define TOT_E     (N_EDGES + N_NODES)   // + self loops
#define F_INDIM   22
#define C_DIM     64
#define H_HEADS   4
#define HC        256
#define G_GRAPHS  20
#define NODES_PG  1000
#define OUT_DIM   128
#define NEG_SLOPE 0.2f

// ---------------- scratch (static device globals; no allocation) ----------------
__device__ float g_hA[N_NODES * HC];
__device__ float g_hB[N_NODES * HC];
__device__ float g_xl[N_NODES * HC];
__device__ float g_xr[N_NODES * HC];
__device__ float g_xg[G_GRAPHS * 2 * HC];
__device__ int   g_cnt[N_NODES];
__device__ int   g_rowptr[N_NODES + 1];
__device__ int   g_fill[N_NODES];
__device__ int   g_col[TOT_E];

// ---------------- input projection: h = relu(x @ Win + bin) ----------------
__global__ void input_proj_kernel(const float* __restrict__ x,
                                  const float* __restrict__ Win,
                                  const float* __restrict__ bin) {
    int node = blockIdx.x;
    int c = threadIdx.x;                 // 64 threads
    __shared__ float xs[F_INDIM];
    if (c < F_INDIM) xs[c] = x[node * F_INDIM + c];
    __syncthreads();
    float acc = bin[c];
#pragma unroll
    for (int k = 0; k < F_INDIM; k++)
        acc = fmaf(xs[k], Win[k * C_DIM + c], acc);
    g_hA[node * C_DIM + c] = fmaxf(acc, 0.f);
}

// ---------------- CSR build ----------------
__global__ void init_cnt_kernel() {
    int i = blockIdx.x * blockDim.x + threadIdx.x;
    if (i < N_NODES) g_cnt[i] = 1;       // self loop pre-counted
}

__global__ void hist_kernel(const int* __restrict__ dst) {
    int e = blockIdx.x * blockDim.x + threadIdx.x;
    if (e < N_EDGES) atomicAdd(&g_cnt[dst[e]], 1);
}

// single-block chunked Hillis-Steele scan over 20000 counts -> exclusive row_ptr
__global__ void scan_kernel() {
    __shared__ int sh[1024];
    __shared__ int carry;
    int tid = threadIdx.x;
    if (tid == 0) { carry = 0; g_rowptr[0] = 0; }
    __syncthreads();
    for (int base = 0; base < N_NODES; base += 1024) {
        int i = base + tid;
        int v = (i < N_NODES) ? g_cnt[i] : 0;
        sh[tid] = v;
        __syncthreads();
        for (int off = 1; off < 1024; off <<= 1) {
            int t = (tid >= off) ? sh[tid - off] : 0;
            __syncthreads();
            sh[tid] += t;
            __syncthreads();
        }
        if (i < N_NODES) g_rowptr[i + 1] = carry + sh[tid];
        __syncthreads();
        if (tid == 1023) carry += sh[1023];
        __syncthreads();
    }
}

// place self loop first in each row, set fill cursor
__global__ void init_fill_kernel() {
    int i = blockIdx.x * blockDim.x + threadIdx.x;
    if (i < N_NODES) {
        int p = g_rowptr[i];
        g_col[p] = i;
        g_fill[i] = p + 1;
    }
}

__global__ void scatter_kernel(const int* __restrict__ src,
                               const int* __restrict__ dst) {
    int e = blockIdx.x * blockDim.x + threadIdx.x;
    if (e < N_EDGES) {
        int pos = atomicAdd(&g_fill[dst[e]], 1);
        g_col[pos] = src[e];
    }
}

// ---------------- fp32 tiled SGEMM: C[M,256] = A[M,K] @ B[K,256] ----------------
#define BM 64
#define BN 64
#define BK 16
__global__ void sgemm_kernel(const float* __restrict__ A,
                             const float* __restrict__ B,
                             float* __restrict__ C, int M, int K) {
    __shared__ float As[BM][BK + 1];
    __shared__ float Bs[BK][BN];
    const int NDIM = HC;                 // 256
    int tid = threadIdx.x;               // 256
    int tx = tid & 15, ty = tid >> 4;
    int row0 = blockIdx.y * BM;
    int col0 = blockIdx.x * BN;
    float acc[4][4] = {};
    for (int k0 = 0; k0 < K; k0 += BK) {
#pragma unroll
        for (int i = 0; i < 4; i++) {
            int e = tid + i * 256;
            // A tile: m = e>>4, kk = e&15  (coalesced 16-wide)
            int m = e >> 4, kk = e & 15;
            int gr = row0 + m;
            As[m][kk] = (gr < M) ? A[gr * K + k0 + kk] : 0.f;
            // B tile: kk = e>>6, n = e&63 (coalesced 64-wide)
            int kb = e >> 6, n = e & 63;
            Bs[kb][n] = B[(k0 + kb) * NDIM + col0 + n];
        }
        __syncthreads();
#pragma unroll
        for (int kk = 0; kk < BK; kk++) {
            float ra[4], rb[4];
#pragma unroll
            for (int i = 0; i < 4; i++) ra[i] = As[ty * 4 + i][kk];
#pragma unroll
            for (int j = 0; j < 4; j++) rb[j] = Bs[kk][tx * 4 + j];
#pragma unroll
            for (int i = 0; i < 4; i++)
#pragma unroll
                for (int j = 0; j < 4; j++)
                    acc[i][j] = fmaf(ra[i], rb[j], acc[i][j]);
        }
        __syncthreads();
    }
#pragma unroll
    for (int i = 0; i < 4; i++) {
        int gr = row0 + ty * 4 + i;
        if (gr < M) {
#pragma unroll
            for (int j = 0; j < 4; j++)
                C[gr * NDIM + col0 + tx * 4 + j] = acc[i][j];
        }
    }
}

// ---------------- fused GATv2 edge kernel (warp per node, online softmax) ----
// lane l owns channels [8l, 8l+8); head = l>>3 (64 ch/head)
__global__ void gat_edge_kernel(const float* __restrict__ xl,
                                const float* __restrict__ xr,
                                const float* __restrict__ att,
                                const float* __restrict__ bias,
                                const float* __restrict__ hprev,
                                float* __restrict__ hout,
                                int residual) {
    int gw = (blockIdx.x * blockDim.x + threadIdx.x) >> 5;
    if (gw >= N_NODES) return;
    int lane = threadIdx.x & 31;
    int cbase = lane * 8;

    // per-lane slices of xr[node] and att
    float xr_r[8], att_r[8];
    {
        const float4* p = (const float4*)&xr[gw * HC + cbase];
        float4 a = p[0], b = p[1];
        xr_r[0]=a.x; xr_r[1]=a.y; xr_r[2]=a.z; xr_r[3]=a.w;
        xr_r[4]=b.x; xr_r[5]=b.y; xr_r[6]=b.z; xr_r[7]=b.w;
        const float4* q = (const float4*)&att[cbase];
        float4 c = q[0], d = q[1];
        att_r[0]=c.x; att_r[1]=c.y; att_r[2]=c.z; att_r[3]=c.w;
        att_r[4]=d.x; att_r[5]=d.y; att_r[6]=d.z; att_r[7]=d.w;
    }

    int e0 = g_rowptr[gw];
    int e1 = g_rowptr[gw + 1];

    float m = -INFINITY, den = 0.f;
    float acc[8] = {0.f,0.f,0.f,0.f,0.f,0.f,0.f,0.f};

    for (int e = e0; e < e1; e++) {
        int s = g_col[e];
        const float4* p = (const float4*)&xl[s * HC + cbase];
        float4 a = p[0], b = p[1];
        float xv[8];
        xv[0]=a.x; xv[1]=a.y; xv[2]=a.z; xv[3]=a.w;
        xv[4]=b.x; xv[5]=b.y; xv[6]=b.z; xv[7]=b.w;

        float partial = 0.f;
#pragma unroll
        for (int j = 0; j < 8; j++) {
            float t = xv[j] + xr_r[j];
            t = fmaxf(t, NEG_SLOPE * t);      // leaky_relu
            partial = fmaf(t, att_r[j], partial);
        }
        // reduce over the 8 lanes of this head
        partial += __shfl_xor_sync(0xffffffffu, partial, 1);
        partial += __shfl_xor_sync(0xffffffffu, partial, 2);
        partial += __shfl_xor_sync(0xffffffffu, partial, 4);
        float logit = partial;

        float m_new = fmaxf(m, logit);
        float scale = __expf(m - m_new);      // exp(-inf)=0 on first edge
        float pxe = __expf(logit - m_new);
        den = den * scale + pxe;
#pragma unroll
        for (int j = 0; j < 8; j++)
            acc[j] = fmaf(acc[j], scale, pxe * xv[j]);
        m = m_new;
    }

    float inv = 1.f / (den + 1e-16f);
#pragma unroll
    for (int j = 0; j < 8; j++) {
        float v = fmaf(acc[j], inv, bias[cbase + j]);
        v = (v > 0.f) ? v : (__expf(v) - 1.f);            // ELU
        if (residual) v += hprev[gw * HC + cbase + j];
        hout[gw * HC + cbase + j] = v;
    }
}

// ---------------- pooling: mean + max per graph ----------------
__global__ void pool_kernel(const float* __restrict__ h) {
    int g = blockIdx.x;
    int c = threadIdx.x;                   // 256
    const float* base = h + (size_t)g * NODES_PG * HC;
    float s = 0.f, mx = -INFINITY;
    for (int n = 0; n < NODES_PG; n++) {
        float v = base[n * HC + c];
        s += v;
        mx = fmaxf(mx, v);
    }
    g_xg[g * (2 * HC) + c]      = s * (1.f / NODES_PG);
    g_xg[g * (2 * HC) + HC + c] = mx;
}

// ---------------- head: out = x_global @ Wout + bout ----------------
__global__ void head_kernel(const float* __restrict__ Wout,
                            const float* __restrict__ bout,
                            float* __restrict__ out) {
    int g = blockIdx.x;
    int o = threadIdx.x;                   // 128
    float acc = bout[o];
    const float* xg = &g_xg[g * 2 * HC];
#pragma unroll 8
    for (int k = 0; k < 2 * HC; k++)
        acc = fmaf(xg[k], Wout[k * OUT_DIM + o], acc);
    out[g * OUT_DIM + o] = acc;
}

// ---------------- launch ----------------
extern "C" void kernel_launch(void* const* d_in, const int* in_sizes, int n_in,
                              void* d_out, int out_size) {
    const float* x    = (const float*)d_in[0];
    const int*   ei   = (const int*)d_in[1];     // [2, E] int32: row0 src, row1 dst
    // d_in[2] = batch (recomputed on device as node/1000; unused)
    const float* Win  = (const float*)d_in[3];
    const float* bin  = (const float*)d_in[4];
    const float* Wout = (const float*)d_in[5];
    const float* bout = (const float*)d_in[6];
    const float* Wl[3] = { (const float*)d_in[7],  (const float*)d_in[11], (const float*)d_in[15] };
    const float* Wr[3] = { (const float*)d_in[8],  (const float*)d_in[12], (const float*)d_in[16] };
    const float* At[3] = { (const float*)d_in[9],  (const float*)d_in[13], (const float*)d_in[17] };
    const float* Bi[3] = { (const float*)d_in[10], (const float*)d_in[14], (const float*)d_in[18] };
    float* out = (float*)d_out;

    const int* src = ei;
    const int* dst = ei + N_EDGES;

    float *hA, *hB, *xl, *xr;
    cudaGetSymbolAddress((void**)&hA, g_hA);
    cudaGetSymbolAddress((void**)&hB, g_hB);
    cudaGetSymbolAddress((void**)&xl, g_xl);
    cudaGetSymbolAddress((void**)&xr, g_xr);

    // CSR build (also overlaps conceptually with input proj; same stream keeps order)
    init_cnt_kernel<<<(N_NODES + 255) / 256, 256>>>();
    hist_kernel<<<(N_EDGES + 255) / 256, 256>>>(dst);
    scan_kernel<<<1, 1024>>>();
    init_fill_kernel<<<(N_NODES + 255) / 256, 256>>>();
    scatter_kernel<<<(N_EDGES + 255) / 256, 256>>>(src, dst);

    // input projection -> hA [N, 64]
    input_proj_kernel<<<N_NODES, C_DIM>>>(x, Win, bin);

    dim3 ggrid(HC / BN, (N_NODES + BM - 1) / BM);
    const int EDGE_THREADS = 256;
    int edge_blocks = (N_NODES * 32 + EDGE_THREADS - 1) / EDGE_THREADS;

    // layer 0: in hA (K=64) -> out hB, no residual
    sgemm_kernel<<<ggrid, 256>>>(hA, Wl[0], xl, N_NODES, C_DIM);
    sgemm_kernel<<<ggrid, 256>>>(hA, Wr[0], xr, N_NODES, C_DIM);
    gat_edge_kernel<<<edge_blocks, EDGE_THREADS>>>(xl, xr, At[0], Bi[0], hA, hB, 0);

    // layer 1: in hB (K=256) -> out hA, residual hB
    sgemm_kernel<<<ggrid, 256>>>(hB, Wl[1], xl, N_NODES, HC);
    sgemm_kernel<<<ggrid, 256>>>(hB, Wr[1], xr, N_NODES, HC);
    gat_edge_kernel<<<edge_blocks, EDGE_THREADS>>>(xl, xr, At[1], Bi[1], hB, hA, 1);

    // layer 2: in hA -> out hB, residual hA
    sgemm_kernel<<<ggrid, 256>>>(hA, Wl[2], xl, N_NODES, HC);
    sgemm_kernel<<<ggrid, 256>>>(hA, Wr[2], xr, N_NODES, HC);
    gat_edge_kernel<<<edge_blocks, EDGE_THREADS>>>(xl, xr, At[2], Bi[2], hA, hB, 1);

    // pooling + head
    pool_kernel<<<G_GRAPHS, HC>>>(hB);
    head_kernel<<<G_GRAPHS, OUT_DIM>>>(Wout, bout, out);
}

// round 2
// speedup vs baseline: 1.2948x; 1.2948x over previous
#include <cuda_runtime.h>
#include <math.h>

// ---------------- problem constants ----------------
#define N_NODES   20000
#define N_EDGES   320000
#define TOT_E     (N_EDGES + N_NODES)   // + self loops
#define F_INDIM   22
#define C_DIM     64
#define H_HEADS   4
#define HC        256
#define NLR       512                   // fused xl|xr row width
#define G_GRAPHS  20
#define NODES_PG  1000
#define OUT_DIM   128
#define NEG_SLOPE 0.2f

// ---------------- scratch (static device globals; no allocation) ----------------
__device__ float g_hA[N_NODES * HC];
__device__ float g_hB[N_NODES * HC];
__device__ float g_xlr[N_NODES * NLR];      // [node][xl(256) | xr(256)]
__device__ float g_xg[G_GRAPHS * 2 * HC];
__device__ float g_poolP[G_GRAPHS * 8 * 2 * HC];
__device__ int   g_cnt[N_NODES];
__device__ int   g_rowptr[N_NODES + 1];
__device__ int   g_fill[N_NODES];
__device__ int   g_col[TOT_E];
__device__ int   g_blk[128];

// ---------------- input projection: h = relu(x @ Win + bin) ----------------
__global__ void input_proj_kernel(const float* __restrict__ x,
                                  const float* __restrict__ Win,
                                  const float* __restrict__ bin) {
    int node = blockIdx.x;
    int c = threadIdx.x;                 // 64 threads
    __shared__ float xs[F_INDIM];
    if (c < F_INDIM) xs[c] = x[node * F_INDIM + c];
    __syncthreads();
    float acc = bin[c];
#pragma unroll
    for (int k = 0; k < F_INDIM; k++)
        acc = fmaf(xs[k], Win[k * C_DIM + c], acc);
    g_hA[node * C_DIM + c] = fmaxf(acc, 0.f);
}

// ---------------- CSR build ----------------
__global__ void init_cnt_kernel() {
    int i = blockIdx.x * blockDim.x + threadIdx.x;
    if (i < N_NODES) g_cnt[i] = 1;       // self loop pre-counted
}

__global__ void hist_kernel(const int* __restrict__ dst) {
    int e = blockIdx.x * blockDim.x + threadIdx.x;
    if (e < N_EDGES) atomicAdd(&g_cnt[dst[e]], 1);
}

// two-level scan: (1) per-block inclusive scan, (2) scan of block totals,
// (3) add offsets
__global__ void scan1_kernel() {
    __shared__ int sh[256];
    int t = threadIdx.x;
    int i = blockIdx.x * 256 + t;
    int v = (i < N_NODES) ? g_cnt[i] : 0;
    sh[t] = v;
    __syncthreads();
#pragma unroll
    for (int off = 1; off < 256; off <<= 1) {
        int x = (t >= off) ? sh[t - off] : 0;
        __syncthreads();
        sh[t] += x;
        __syncthreads();
    }
    if (i < N_NODES) g_rowptr[i + 1] = sh[t];
    if (t == 255) g_blk[blockIdx.x] = sh[255];
}

__global__ void scan2_kernel(int nblk) {
    __shared__ int sh[128];
    int t = threadIdx.x;
    if (t < nblk) sh[t] = g_blk[t];
    __syncthreads();
    if (t == 0) {
        int run = 0;
        for (int i = 0; i < nblk; i++) { int v = sh[i]; sh[i] = run; run += v; }
    }
    __syncthreads();
    if (t < nblk) g_blk[t] = sh[t];
}

__global__ void scan3_kernel() {
    int i = blockIdx.x * 256 + threadIdx.x;
    if (i < N_NODES) g_rowptr[i + 1] += g_blk[blockIdx.x];
    if (i == 0) g_rowptr[0] = 0;
}

// place self loop first in each row, set fill cursor
__global__ void init_fill_kernel() {
    int i = blockIdx.x * blockDim.x + threadIdx.x;
    if (i < N_NODES) {
        int p = g_rowptr[i];
        g_col[p] = i;
        g_fill[i] = p + 1;
    }
}

__global__ void scatter_kernel(const int* __restrict__ src,
                               const int* __restrict__ dst) {
    int e = blockIdx.x * blockDim.x + threadIdx.x;
    if (e < N_EDGES) {
        int pos = atomicAdd(&g_fill[dst[e]], 1);
        g_col[pos] = src[e];
    }
}

// ---------------- TF32 tensor-core GEMM ----------------
// C[M, 512] = A[M,K] @ [Wl | Wr]  (Wl,Wr each [K,256] row-major)
// block tile 128x64, BK=32, 256 threads (8 warps as 4m x 2n, warp tile 32x32)
#define GBM 128
#define GBN 64
#define GBK 32
#define APAD 36
#define BPAD 72
#define ABUF (GBM * APAD)                 // 4608 floats
#define BBUF (GBK * BPAD)                 // 2304 floats
#define BUFSZ (ABUF + BBUF)               // 6912 floats per stage
#define GEMM_SMEM (2 * BUFSZ * 4)         // 55296 bytes

__device__ __forceinline__ float tf32r(float x) {
    unsigned u;
    asm("cvt.rna.tf32.f32 %0, %1;" : "=r"(u) : "f"(x));
    return __uint_as_float(u);
}

__global__ __launch_bounds__(256, 2)
void gemm_tf32_kernel(const float* __restrict__ A,
                      const float* __restrict__ Wl,
                      const float* __restrict__ Wr,
                      float* __restrict__ Cout, int M, int K) {
    extern __shared__ float sm[];
    int tid = threadIdx.x;
    int lane = tid & 31, wid = tid >> 5;
    int warp_m = wid >> 1, warp_n = wid & 1;
    int row0 = blockIdx.y * GBM;
    int col0 = blockIdx.x * GBN;
    const float* W = (col0 < HC) ? Wl : Wr;
    int wc0 = col0 & (HC - 1);

    // staging-register loaders
    int ar = tid >> 3, ac = (tid & 7) * 4;      // A: 128 rows x 8 float4
    int bk = tid >> 4, bc = (tid & 15) * 4;     // B: 32 rows x 16 float4
    float4 aReg[4], bReg[2];

    auto loadG = [&](int k0) {
#pragma unroll
        for (int i = 0; i < 4; i++) {
            int gr = row0 + ar + 32 * i;
            aReg[i] = (gr < M) ? *(const float4*)&A[(size_t)gr * K + k0 + ac]
                               : make_float4(0.f, 0.f, 0.f, 0.f);
        }
#pragma unroll
        for (int i = 0; i < 2; i++) {
            int kr = bk + 16 * i;
            bReg[i] = *(const float4*)&W[(size_t)(k0 + kr) * HC + wc0 + bc];
        }
    };
    auto storeS = [&](int buf) {
        float* Ab = sm + buf * BUFSZ;
        float* Bb = Ab + ABUF;
#pragma unroll
        for (int i = 0; i < 4; i++) {
            float4 v = aReg[i];
            v.x = tf32r(v.x); v.y = tf32r(v.y); v.z = tf32r(v.z); v.w = tf32r(v.w);
            *(float4*)&Ab[(ar + 32 * i) * APAD + ac] = v;
        }
#pragma unroll
        for (int i = 0; i < 2; i++) {
            float4 v = bReg[i];
            v.x = tf32r(v.x); v.y = tf32r(v.y); v.z = tf32r(v.z); v.w = tf32r(v.w);
            *(float4*)&Bb[(bk + 16 * i) * BPAD + bc] = v;
        }
    };

    float acc[2][4][4] = {};
    int fr = lane >> 2, fk = lane & 3;

    loadG(0);
    storeS(0);
    __syncthreads();

    int nch = K / GBK;
    for (int ch = 0; ch < nch; ch++) {
        if (ch + 1 < nch) loadG((ch + 1) * GBK);
        int buf = ch & 1;
        const float* Ab = sm + buf * BUFSZ;
        const float* Bb = Ab + ABUF;
#pragma unroll
        for (int ks = 0; ks < 4; ks++) {
            int kb = ks * 8;
            unsigned af[2][4];
#pragma unroll
            for (int tm = 0; tm < 2; tm++) {
                const float* p = Ab + (warp_m * 32 + tm * 16 + fr) * APAD + kb + fk;
                af[tm][0] = __float_as_uint(p[0]);
                af[tm][1] = __float_as_uint(p[8 * APAD]);
                af[tm][2] = __float_as_uint(p[4]);
                af[tm][3] = __float_as_uint(p[8 * APAD + 4]);
            }
#pragma unroll
            for (int tn = 0; tn < 4; tn++) {
                int nc = warp_n * 32 + tn * 8 + fr;
                unsigned b0 = __float_as_uint(Bb[(kb + fk) * BPAD + nc]);
                unsigned b1 = __float_as_uint(Bb[(kb + fk + 4) * BPAD + nc]);
#pragma unroll
                for (int tm = 0; tm < 2; tm++) {
                    float* c = acc[tm][tn];
                    asm volatile(
                        "mma.sync.aligned.m16n8k8.row.col.f32.tf32.tf32.f32 "
                        "{%0,%1,%2,%3}, {%4,%5,%6,%7}, {%8,%9}, {%0,%1,%2,%3};"
                        : "+f"(c[0]), "+f"(c[1]), "+f"(c[2]), "+f"(c[3])
                        : "r"(af[tm][0]), "r"(af[tm][1]), "r"(af[tm][2]),
                          "r"(af[tm][3]), "r"(b0), "r"(b1));
                }
            }
        }
        if (ch + 1 < nch) {
            storeS(buf ^ 1);
            __syncthreads();
        }
    }

    // epilogue
#pragma unroll
    for (int tm = 0; tm < 2; tm++) {
#pragma unroll
        for (int tn = 0; tn < 4; tn++) {
            int row = row0 + warp_m * 32 + tm * 16 + fr;
            int col = col0 + warp_n * 32 + tn * 8 + 2 * fk;
            float* c = acc[tm][tn];
            if (row < M) {
                float2 v = make_float2(c[0], c[1]);
                *(float2*)&Cout[(size_t)row * NLR + col] = v;
            }
            if (row + 8 < M) {
                float2 v = make_float2(c[2], c[3]);
                *(float2*)&Cout[(size_t)(row + 8) * NLR + col] = v;
            }
        }
    }
}

// ---------------- fused GATv2 edge kernel (warp per node, online softmax) ----
// lane l owns channels [8l, 8l+8); head = l>>3 (64 ch/head)
__global__ void gat_edge_kernel(const float* __restrict__ xlr,
                                const float* __restrict__ att,
                                const float* __restrict__ bias,
                                const float* __restrict__ hprev,
                                float* __restrict__ hout,
                                int residual) {
    int gw = (blockIdx.x * blockDim.x + threadIdx.x) >> 5;
    if (gw >= N_NODES) return;
    int lane = threadIdx.x & 31;
    int cbase = lane * 8;

    // per-lane slices of xr[node] and att
    float xr_r[8], att_r[8];
    {
        const float4* p = (const float4*)&xlr[(size_t)gw * NLR + HC + cbase];
        float4 a = p[0], b = p[1];
        xr_r[0]=a.x; xr_r[1]=a.y; xr_r[2]=a.z; xr_r[3]=a.w;
        xr_r[4]=b.x; xr_r[5]=b.y; xr_r[6]=b.z; xr_r[7]=b.w;
        const float4* q = (const float4*)&att[cbase];
        float4 c = q[0], d = q[1];
        att_r[0]=c.x; att_r[1]=c.y; att_r[2]=c.z; att_r[3]=c.w;
        att_r[4]=d.x; att_r[5]=d.y; att_r[6]=d.z; att_r[7]=d.w;
    }

    int e0 = g_rowptr[gw];
    int e1 = g_rowptr[gw + 1];

    float m = -INFINITY, den = 0.f;
    float acc[8] = {0.f,0.f,0.f,0.f,0.f,0.f,0.f,0.f};

    for (int e = e0; e < e1; e++) {
        int s = g_col[e];
        const float4* p = (const float4*)&xlr[(size_t)s * NLR + cbase];
        float4 a = p[0], b = p[1];
        float xv[8];
        xv[0]=a.x; xv[1]=a.y; xv[2]=a.z; xv[3]=a.w;
        xv[4]=b.x; xv[5]=b.y; xv[6]=b.z; xv[7]=b.w;

        float partial = 0.f;
#pragma unroll
        for (int j = 0; j < 8; j++) {
            float t = xv[j] + xr_r[j];
            t = fmaxf(t, NEG_SLOPE * t);      // leaky_relu
            partial = fmaf(t, att_r[j], partial);
        }
        // reduce over the 8 lanes of this head
        partial += __shfl_xor_sync(0xffffffffu, partial, 1);
        partial += __shfl_xor_sync(0xffffffffu, partial, 2);
        partial += __shfl_xor_sync(0xffffffffu, partial, 4);
        float logit = partial;

        float m_new = fmaxf(m, logit);
        float scale = __expf(m - m_new);      // exp(-inf)=0 on first edge
        float pxe = __expf(logit - m_new);
        den = den * scale + pxe;
#pragma unroll
        for (int j = 0; j < 8; j++)
            acc[j] = fmaf(acc[j], scale, pxe * xv[j]);
        m = m_new;
    }

    float inv = 1.f / (den + 1e-16f);
#pragma unroll
    for (int j = 0; j < 8; j++) {
        float v = fmaf(acc[j], inv, bias[cbase + j]);
        v = (v > 0.f) ? v : (__expf(v) - 1.f);            // ELU
        if (residual) v += hprev[gw * HC + cbase + j];
        hout[gw * HC + cbase + j] = v;
    }
}

// ---------------- pooling: partial mean+max, then combine ----------------
__global__ void pool1_kernel(const float* __restrict__ h) {
    int g = blockIdx.y, ch = blockIdx.x;       // 8 chunks of 125 nodes
    int c = threadIdx.x;                       // 256
    const float* base = h + ((size_t)g * NODES_PG + ch * 125) * HC;
    float s = 0.f, mx = -INFINITY;
    for (int n = 0; n < 125; n++) {
        float v = base[n * HC + c];
        s += v;
        mx = fmaxf(mx, v);
    }
    float* out = &g_poolP[(size_t)(g * 8 + ch) * 2 * HC];
    out[c] = s;
    out[HC + c] = mx;
}

__global__ void pool2_kernel() {
    int g = blockIdx.x;
    int c = threadIdx.x;                       // 256
    float s = 0.f, mx = -INFINITY;
    for (int ch = 0; ch < 8; ch++) {
        const float* in = &g_poolP[(size_t)(g * 8 + ch) * 2 * HC];
        s += in[c];
        mx = fmaxf(mx, in[HC + c]);
    }
    g_xg[g * (2 * HC) + c]      = s * (1.f / NODES_PG);
    g_xg[g * (2 * HC) + HC + c] = mx;
}

// ---------------- head: out = x_global @ Wout + bout ----------------
__global__ void head_kernel(const float* __restrict__ Wout,
                            const float* __restrict__ bout,
                            float* __restrict__ out) {
    int g = blockIdx.x;
    int o = threadIdx.x;                   // 128
    float acc = bout[o];
    const float* xg = &g_xg[g * 2 * HC];
#pragma unroll 8
    for (int k = 0; k < 2 * HC; k++)
        acc = fmaf(xg[k], Wout[k * OUT_DIM + o], acc);
    out[g * OUT_DIM + o] = acc;
}

// ---------------- launch ----------------
extern "C" void kernel_launch(void* const* d_in, const int* in_sizes, int n_in,
                              void* d_out, int out_size) {
    const float* x    = (const float*)d_in[0];
    const int*   ei   = (const int*)d_in[1];     // [2, E] int32: row0 src, row1 dst
    const float* Win  = (const float*)d_in[3];
    const float* bin  = (const float*)d_in[4];
    const float* Wout = (const float*)d_in[5];
    const float* bout = (const float*)d_in[6];
    const float* Wl[3] = { (const float*)d_in[7],  (const float*)d_in[11], (const float*)d_in[15] };
    const float* Wr[3] = { (const float*)d_in[8],  (const float*)d_in[12], (const float*)d_in[16] };
    const float* At[3] = { (const float*)d_in[9],  (const float*)d_in[13], (const float*)d_in[17] };
    const float* Bi[3] = { (const float*)d_in[10], (const float*)d_in[14], (const float*)d_in[18] };
    float* out = (float*)d_out;

    const int* src = ei;
    const int* dst = ei + N_EDGES;

    float *hA, *hB, *xlr;
    cudaGetSymbolAddress((void**)&hA, g_hA);
    cudaGetSymbolAddress((void**)&hB, g_hB);
    cudaGetSymbolAddress((void**)&xlr, g_xlr);

    cudaFuncSetAttribute(gemm_tf32_kernel,
                         cudaFuncAttributeMaxDynamicSharedMemorySize, GEMM_SMEM);

    const int NB = (N_NODES + 255) / 256;   // 79

    // CSR build
    init_cnt_kernel<<<NB, 256>>>();
    hist_kernel<<<(N_EDGES + 255) / 256, 256>>>(dst);
    scan1_kernel<<<NB, 256>>>();
    scan2_kernel<<<1, 128>>>(NB);
    scan3_kernel<<<NB, 256>>>();
    init_fill_kernel<<<NB, 256>>>();
    scatter_kernel<<<(N_EDGES + 255) / 256, 256>>>(src, dst);

    // input projection -> hA [N, 64]
    input_proj_kernel<<<N_NODES, C_DIM>>>(x, Win, bin);

    dim3 ggrid(NLR / GBN, (N_NODES + GBM - 1) / GBM);     // 8 x 157
    const int EDGE_THREADS = 256;
    int edge_blocks = (N_NODES * 32 + EDGE_THREADS - 1) / EDGE_THREADS;

    // layer 0: in hA (K=64) -> out hB, no residual
    gemm_tf32_kernel<<<ggrid, 256, GEMM_SMEM>>>(hA, Wl[0], Wr[0], xlr, N_NODES, C_DIM);
    gat_edge_kernel<<<edge_blocks, EDGE_THREADS>>>(xlr, At[0], Bi[0], hA, hB, 0);

    // layer 1: in hB (K=256) -> out hA, residual hB
    gemm_tf32_kernel<<<ggrid, 256, GEMM_SMEM>>>(hB, Wl[1], Wr[1], xlr, N_NODES, HC);
    gat_edge_kernel<<<edge_blocks, EDGE_THREADS>>>(xlr, At[1], Bi[1], hB, hA, 1);

    // layer 2: in hA -> out hB, residual hA
    gemm_tf32_kernel<<<ggrid, 256, GEMM_SMEM>>>(hA, Wl[2], Wr[2], xlr, N_NODES, HC);
    gat_edge_kernel<<<edge_blocks, EDGE_THREADS>>>(xlr, At[2], Bi[2], hA, hB, 1);

    // pooling + head
    pool1_kernel<<<dim3(8, G_GRAPHS), HC>>>(hB);
    pool2_kernel<<<G_GRAPHS, HC>>>();
    head_kernel<<<G_GRAPHS, OUT_DIM>>>(Wout, bout, out);
}

// round 4
// speedup vs baseline: 1.9494x; 1.5055x over previous
#include <cuda_runtime.h>
#include <math.h>
#include <stdint.h>

// ---------------- problem constants ----------------
#define N_NODES   20000
#define N_PAD     20096                 // 157 * 128
#define N_EDGES   320000
#define TOT_E     (N_EDGES + N_NODES)   // + self loops
#define F_INDIM   22
#define C_DIM     64
#define H_HEADS   4
#define HC        256
#define NLR       512                   // fused xl|xr row width
#define G_GRAPHS  20
#define NODES_PG  1000
#define OUT_DIM   128
#define NEG_SLOPE 0.2f

// ---------------- scratch (static device globals; no allocation) ----------------
__device__ float g_hA[N_PAD * HC];
__device__ float g_hB[N_PAD * HC];
__device__ float g_xlr[N_PAD * NLR];        // [node][xl(256) | xr(256)]
__device__ float g_xg[G_GRAPHS * 2 * HC];
__device__ float g_poolP[G_GRAPHS * 8 * 2 * HC];
__device__ int   g_cnt[N_NODES];
__device__ int   g_rowptr[N_NODES + 1];
__device__ int   g_fill[N_NODES];
__device__ int   g_col[TOT_E];
__device__ int   g_blk[128];

// ---------------- helpers ----------------
__device__ __forceinline__ uint32_t smem_u32(const void* p) {
    uint32_t a;
    asm("{ .reg .u64 t; cvta.to.shared.u64 t, %1; cvt.u32.u64 %0, t; }"
        : "=r"(a) : "l"(p));
    return a;
}
__device__ __forceinline__ unsigned tf32u(float x) {
    unsigned u;
    asm("cvt.rna.tf32.f32 %0, %1;" : "=r"(u) : "f"(x));
    return u;
}
__device__ __forceinline__ void cp_async16(uint32_t saddr, const void* gaddr) {
    asm volatile("cp.async.cg.shared.global [%0], [%1], 16;"
                 :: "r"(saddr), "l"(gaddr));
}
__device__ __forceinline__ void cp_commit() {
    asm volatile("cp.async.commit_group;" ::: "memory");
}
template <int NN>
__device__ __forceinline__ void cp_wait() {
    asm volatile("cp.async.wait_group %0;" :: "n"(NN) : "memory");
}

// ---------------- input projection: h = relu(x @ Win + bin) ----------------
__global__ void input_proj_kernel(const float* __restrict__ x,
                                  const float* __restrict__ Win,
                                  const float* __restrict__ bin) {
    int node = blockIdx.x;
    int c = threadIdx.x;                 // 64 threads
    __shared__ float xs[F_INDIM];
    if (c < F_INDIM) xs[c] = x[node * F_INDIM + c];
    __syncthreads();
    float acc = bin[c];
#pragma unroll
    for (int k = 0; k < F_INDIM; k++)
        acc = fmaf(xs[k], Win[k * C_DIM + c], acc);
    g_hA[node * C_DIM + c] = fmaxf(acc, 0.f);
}

// ---------------- CSR build ----------------
__global__ void init_cnt_kernel() {
    int i = blockIdx.x * blockDim.x + threadIdx.x;
    if (i < N_NODES) g_cnt[i] = 1;       // self loop pre-counted
}

__global__ void hist_kernel(const int* __restrict__ dst) {
    int e = blockIdx.x * blockDim.x + threadIdx.x;
    if (e < N_EDGES) atomicAdd(&g_cnt[dst[e]], 1);
}

__global__ void scan1_kernel() {
    __shared__ int sh[256];
    int t = threadIdx.x;
    int i = blockIdx.x * 256 + t;
    int v = (i < N_NODES) ? g_cnt[i] : 0;
    sh[t] = v;
    __syncthreads();
#pragma unroll
    for (int off = 1; off < 256; off <<= 1) {
        int x = (t >= off) ? sh[t - off] : 0;
        __syncthreads();
        sh[t] += x;
        __syncthreads();
    }
    if (i < N_NODES) g_rowptr[i + 1] = sh[t];
    if (t == 255) g_blk[blockIdx.x] = sh[255];
}

__global__ void scan2_kernel(int nblk) {
    __shared__ int sh[128];
    int t = threadIdx.x;
    if (t < nblk) sh[t] = g_blk[t];
    __syncthreads();
    if (t == 0) {
        int run = 0;
        for (int i = 0; i < nblk; i++) { int v = sh[i]; sh[i] = run; run += v; }
    }
    __syncthreads();
    if (t < nblk) g_blk[t] = sh[t];
}

__global__ void scan3_kernel() {
    int i = blockIdx.x * 256 + threadIdx.x;
    if (i < N_NODES) g_rowptr[i + 1] += g_blk[blockIdx.x];
    if (i == 0) g_rowptr[0] = 0;
}

__global__ void init_fill_kernel() {
    int i = blockIdx.x * blockDim.x + threadIdx.x;
    if (i < N_NODES) {
        int p = g_rowptr[i];
        g_col[p] = i;
        g_fill[i] = p + 1;
    }
}

__global__ void scatter_kernel(const int* __restrict__ src,
                               const int* __restrict__ dst) {
    int e = blockIdx.x * blockDim.x + threadIdx.x;
    if (e < N_EDGES) {
        int pos = atomicAdd(&g_fill[dst[e]], 1);
        g_col[pos] = src[e];
    }
}

// ---------------- TF32 mma.sync GEMM, cp.async 3-stage pipeline ----------------
// C[N_PAD, 512] = A[N_PAD, K] @ [Wl | Wr]   (Wl, Wr each [K,256] row-major)
// CTA tile 128x128, 8 warps (2m x 4n), warp tile 64x32, BK=32.
#define GBM 128
#define GBN 128
#define GBK 32
#define APITCH 36
#define BPITCH 132
#define A_ST (GBM * APITCH)                  // 4608 floats
#define B_ST (GBK * BPITCH)                  // 4224 floats
#define STAGE_FLOATS (A_ST + B_ST)           // 8832 floats
#define STG 3
#define GEMM_SMEM (STG * STAGE_FLOATS * 4)   // 105984 bytes

__global__ __launch_bounds__(256, 2)
void gemm_tf32_kernel(const float* __restrict__ A,
                      const float* __restrict__ Wl,
                      const float* __restrict__ Wr,
                      float* __restrict__ Cout, int K) {
    extern __shared__ float sm[];
    const uint32_t sbase = smem_u32(sm);

    int tid = threadIdx.x;
    int lane = tid & 31, wid = tid >> 5;
    int warp_m = wid >> 2;           // 0..1 (64 rows)
    int warp_n = wid & 3;            // 0..3 (32 cols)
    int fr = lane >> 2, fk = lane & 3;

    int row0 = blockIdx.y * GBM;
    int col0 = blockIdx.x * GBN;
    const float* W = (blockIdx.x < 2) ? Wl : Wr;
    int wc0 = (blockIdx.x & 1) * 128;

    const int nch = K / GBK;

    auto issue = [&](int ch) {
        uint32_t sA = sbase + (uint32_t)(ch % STG) * (STAGE_FLOATS * 4);
        uint32_t sB = sA + A_ST * 4;
        const float* aG = A + (size_t)row0 * K + ch * GBK;
        const float* bG = W + (size_t)(ch * GBK) * HC + wc0;
#pragma unroll
        for (int i = 0; i < 4; i++) {
            int idx = tid + i * 256;          // 1024 float4 for A
            int m = idx >> 3, q = idx & 7;
            cp_async16(sA + (uint32_t)(m * APITCH + q * 4) * 4,
                       aG + (size_t)m * K + q * 4);
        }
#pragma unroll
        for (int i = 0; i < 4; i++) {
            int idx = tid + i * 256;          // 1024 float4 for B
            int k = idx >> 5, n4 = idx & 31;
            cp_async16(sB + (uint32_t)(k * BPITCH + n4 * 4) * 4,
                       bG + (size_t)k * HC + n4 * 4);
        }
        cp_commit();
    };

    // prologue: fill up to STG-1 stages
    for (int p = 0; p < STG - 1 && p < nch; p++) issue(p);

    float acc[4][4][4] = {};

    for (int ch = 0; ch < nch; ch++) {
        if (ch >= nch - 1) cp_wait<0>(); else cp_wait<1>();
        __syncthreads();
        if (ch + STG - 1 < nch) issue(ch + STG - 1);

        const float* Ab = sm + (ch % STG) * STAGE_FLOATS;
        const float* Bb = Ab + A_ST;
#pragma unroll
        for (int ks = 0; ks < 4; ks++) {
            int kb = ks * 8;
            unsigned af[4][4];
#pragma unroll
            for (int mt = 0; mt < 4; mt++) {
                const float* p = Ab + (warp_m * 64 + mt * 16 + fr) * APITCH + kb + fk;
                af[mt][0] = tf32u(p[0]);
                af[mt][1] = tf32u(p[8 * APITCH]);
                af[mt][2] = tf32u(p[4]);
                af[mt][3] = tf32u(p[8 * APITCH + 4]);
            }
            unsigned bf[4][2];
#pragma unroll
            for (int nt = 0; nt < 4; nt++) {
                int nc = warp_n * 32 + nt * 8 + fr;
                bf[nt][0] = tf32u(Bb[(kb + fk) * BPITCH + nc]);
                bf[nt][1] = tf32u(Bb[(kb + fk + 4) * BPITCH + nc]);
            }
#pragma unroll
            for (int mt = 0; mt < 4; mt++)
#pragma unroll
                for (int nt = 0; nt < 4; nt++) {
                    float* c = acc[mt][nt];
                    asm volatile(
                        "mma.sync.aligned.m16n8k8.row.col.f32.tf32.tf32.f32 "
                        "{%0,%1,%2,%3}, {%4,%5,%6,%7}, {%8,%9}, {%0,%1,%2,%3};"
                        : "+f"(c[0]), "+f"(c[1]), "+f"(c[2]), "+f"(c[3])
                        : "r"(af[mt][0]), "r"(af[mt][1]), "r"(af[mt][2]),
                          "r"(af[mt][3]), "r"(bf[nt][0]), "r"(bf[nt][1]));
                }
        }
        __syncthreads();
    }

    // epilogue (rows padded: no guards)
#pragma unroll
    for (int mt = 0; mt < 4; mt++) {
#pragma unroll
        for (int nt = 0; nt < 4; nt++) {
            int row = row0 + warp_m * 64 + mt * 16 + fr;
            int col = col0 + warp_n * 32 + nt * 8 + 2 * fk;
            float* c = acc[mt][nt];
            *(float2*)&Cout[(size_t)row * NLR + col] = make_float2(c[0], c[1]);
            *(float2*)&Cout[(size_t)(row + 8) * NLR + col] = make_float2(c[2], c[3]);
        }
    }
}

// ---------------- fused GATv2 edge kernel (warp per node, online softmax) ----
__global__ void gat_edge_kernel(const float* __restrict__ xlr,
                                const float* __restrict__ att,
                                const float* __restrict__ bias,
                                const float* __restrict__ hprev,
                                float* __restrict__ hout,
                                int residual) {
    int gw = (blockIdx.x * blockDim.x + threadIdx.x) >> 5;
    if (gw >= N_NODES) return;
    int lane = threadIdx.x & 31;
    int cbase = lane * 8;

    float xr_r[8], att_r[8];
    {
        const float4* p = (const float4*)&xlr[(size_t)gw * NLR + HC + cbase];
        float4 a = p[0], b = p[1];
        xr_r[0]=a.x; xr_r[1]=a.y; xr_r[2]=a.z; xr_r[3]=a.w;
        xr_r[4]=b.x; xr_r[5]=b.y; xr_r[6]=b.z; xr_r[7]=b.w;
        const float4* q = (const float4*)&att[cbase];
        float4 c = q[0], d = q[1];
        att_r[0]=c.x; att_r[1]=c.y; att_r[2]=c.z; att_r[3]=c.w;
        att_r[4]=d.x; att_r[5]=d.y; att_r[6]=d.z; att_r[7]=d.w;
    }

    int e0 = g_rowptr[gw];
    int e1 = g_rowptr[gw + 1];

    float m = -INFINITY, den = 0.f;
    float acc[8] = {0.f,0.f,0.f,0.f,0.f,0.f,0.f,0.f};

    for (int e = e0; e < e1; e++) {
        int s = g_col[e];
        const float4* p = (const float4*)&xlr[(size_t)s * NLR + cbase];
        float4 a = p[0], b = p[1];
        float xv[8];
        xv[0]=a.x; xv[1]=a.y; xv[2]=a.z; xv[3]=a.w;
        xv[4]=b.x; xv[5]=b.y; xv[6]=b.z; xv[7]=b.w;

        float partial = 0.f;
#pragma unroll
        for (int j = 0; j < 8; j++) {
            float t = xv[j] + xr_r[j];
            t = fmaxf(t, NEG_SLOPE * t);      // leaky_relu
            partial = fmaf(t, att_r[j], partial);
        }
        partial += __shfl_xor_sync(0xffffffffu, partial, 1);
        partial += __shfl_xor_sync(0xffffffffu, partial, 2);
        partial += __shfl_xor_sync(0xffffffffu, partial, 4);
        float logit = partial;

        float m_new = fmaxf(m, logit);
        float scale = __expf(m - m_new);
        float pxe = __expf(logit - m_new);
        den = den * scale + pxe;
#pragma unroll
        for (int j = 0; j < 8; j++)
            acc[j] = fmaf(acc[j], scale, pxe * xv[j]);
        m = m_new;
    }

    float inv = 1.f / (den + 1e-16f);
#pragma unroll
    for (int j = 0; j < 8; j++) {
        float v = fmaf(acc[j], inv, bias[cbase + j]);
        v = (v > 0.f) ? v : (__expf(v) - 1.f);            // ELU
        if (residual) v += hprev[gw * HC + cbase + j];
        hout[gw * HC + cbase + j] = v;
    }
}

// ---------------- pooling: partial mean+max, then combine ----------------
__global__ void pool1_kernel(const float* __restrict__ h) {
    int g = blockIdx.y, ch = blockIdx.x;       // 8 chunks of 125 nodes
    int c = threadIdx.x;                       // 256
    const float* base = h + ((size_t)g * NODES_PG + ch * 125) * HC;
    float s = 0.f, mx = -INFINITY;
    for (int n = 0; n < 125; n++) {
        float v = base[n * HC + c];
        s += v;
        mx = fmaxf(mx, v);
    }
    float* out = &g_poolP[(size_t)(g * 8 + ch) * 2 * HC];
    out[c] = s;
    out[HC + c] = mx;
}

__global__ void pool2_kernel() {
    int g = blockIdx.x;
    int c = threadIdx.x;                       // 256
    float s = 0.f, mx = -INFINITY;
    for (int ch = 0; ch < 8; ch++) {
        const float* in = &g_poolP[(size_t)(g * 8 + ch) * 2 * HC];
        s += in[c];
        mx = fmaxf(mx, in[HC + c]);
    }
    g_xg[g * (2 * HC) + c]      = s * (1.f / NODES_PG);
    g_xg[g * (2 * HC) + HC + c] = mx;
}

// ---------------- head: out = x_global @ Wout + bout ----------------
__global__ void head_kernel(const float* __restrict__ Wout,
                            const float* __restrict__ bout,
                            float* __restrict__ out) {
    int g = blockIdx.x;
    int o = threadIdx.x;                   // 128
    float acc = bout[o];
    const float* xg = &g_xg[g * 2 * HC];
#pragma unroll 8
    for (int k = 0; k < 2 * HC; k++)
        acc = fmaf(xg[k], Wout[k * OUT_DIM + o], acc);
    out[g * OUT_DIM + o] = acc;
}

// ---------------- launch ----------------
extern "C" void kernel_launch(void* const* d_in, const int* in_sizes, int n_in,
                              void* d_out, int out_size) {
    const float* x    = (const float*)d_in[0];
    const int*   ei   = (const int*)d_in[1];     // [2, E] int32: row0 src, row1 dst
    const float* Win  = (const float*)d_in[3];
    const float* bin  = (const float*)d_in[4];
    const float* Wout = (const float*)d_in[5];
    const float* bout = (const float*)d_in[6];
    const float* Wl[3] = { (const float*)d_in[7],  (const float*)d_in[11], (const float*)d_in[15] };
    const float* Wr[3] = { (const float*)d_in[8],  (const float*)d_in[12], (const float*)d_in[16] };
    const float* At[3] = { (const float*)d_in[9],  (const float*)d_in[13], (const float*)d_in[17] };
    const float* Bi[3] = { (const float*)d_in[10], (const float*)d_in[14], (const float*)d_in[18] };
    float* out = (float*)d_out;

    const int* src = ei;
    const int* dst = ei + N_EDGES;

    float *hA, *hB, *xlr;
    cudaGetSymbolAddress((void**)&hA, g_hA);
    cudaGetSymbolAddress((void**)&hB, g_hB);
    cudaGetSymbolAddress((void**)&xlr, g_xlr);

    cudaFuncSetAttribute(gemm_tf32_kernel,
                         cudaFuncAttributeMaxDynamicSharedMemorySize, GEMM_SMEM);

    const int NB = (N_NODES + 255) / 256;   // 79

    // CSR build
    init_cnt_kernel<<<NB, 256>>>();
    hist_kernel<<<(N_EDGES + 255) / 256, 256>>>(dst);
    scan1_kernel<<<NB, 256>>>();
    scan2_kernel<<<1, 128>>>(NB);
    scan3_kernel<<<NB, 256>>>();
    init_fill_kernel<<<NB, 256>>>();
    scatter_kernel<<<(N_EDGES + 255) / 256, 256>>>(src, dst);

    // input projection -> hA [N, 64]
    input_proj_kernel<<<N_NODES, C_DIM>>>(x, Win, bin);

    dim3 ggrid(4, N_PAD / GBM);               // 4 N-tiles x 157 M-tiles
    const int EDGE_THREADS = 256;
    int edge_blocks = (N_NODES * 32 + EDGE_THREADS - 1) / EDGE_THREADS;

    // layer 0: in hA (K=64) -> out hB, no residual
    gemm_tf32_kernel<<<ggrid, 256, GEMM_SMEM>>>(hA, Wl[0], Wr[0], xlr, C_DIM);
    gat_edge_kernel<<<edge_blocks, EDGE_THREADS>>>(xlr, At[0], Bi[0], hA, hB, 0);

    // layer 1: in hB (K=256) -> out hA, residual hB
    gemm_tf32_kernel<<<ggrid, 256, GEMM_SMEM>>>(hB, Wl[1], Wr[1], xlr, HC);
    gat_edge_kernel<<<edge_blocks, EDGE_THREADS>>>(xlr, At[1], Bi[1], hB, hA, 1);

    // layer 2: in hA -> out hB, residual hA
    gemm_tf32_kernel<<<ggrid, 256, GEMM_SMEM>>>(hA, Wl[2], Wr[2], xlr, HC);
    gat_edge_kernel<<<edge_blocks, EDGE_THREADS>>>(xlr, At[2], Bi[2], hA, hB, 1);

    // pooling + head
    pool1_kernel<<<dim3(8, G_GRAPHS), HC>>>(hB);
    pool2_kernel<<<G_GRAPHS, HC>>>();
    head_kernel<<<G_GRAPHS, OUT_DIM>>>(Wout, bout, out);
}

// round 6
// speedup vs baseline: 2.5076x; 1.2863x over previous
#include <cuda_runtime.h>
#include <cuda_fp16.h>
#include <math.h>
#include <stdint.h>

// ---------------- problem constants ----------------
#define N_NODES   20000
#define N_PAD     20096                 // 157 * 128
#define N_EDGES   320000
#define TOT_E     (N_EDGES + N_NODES)   // + self loops
#define F_INDIM   22
#define C_DIM     64
#define H_HEADS   4
#define HC        256
#define NLR       512                   // fused xl|xr row width
#define G_GRAPHS  20
#define NODES_PG  1000
#define OUT_DIM   128
#define NEG_SLOPE 0.2f

// ---------------- scratch (static device globals; no allocation) ----------------
__device__ __half g_hA[N_PAD * HC];
__device__ __half g_hB[N_PAD * HC];
__device__ __half g_xlr[N_PAD * NLR];       // [node][xl(256) | xr(256)]
__device__ __half g_Wt0[NLR * C_DIM];       // layer0 weights, [n][k] fp16
__device__ __half g_Wt1[NLR * HC];
__device__ __half g_Wt2[NLR * HC];
__device__ float  g_xg[G_GRAPHS * 2 * HC];
__device__ float  g_poolP[G_GRAPHS * 8 * 2 * HC];
__device__ int    g_cnt[N_NODES];
__device__ int    g_rowptr[N_NODES + 1];
__device__ int    g_fill[N_NODES];
__device__ int    g_col[TOT_E];
__device__ int    g_blk[128];

// ---------------- helpers ----------------
__device__ __forceinline__ uint32_t smem_u32(const void* p) {
    uint32_t a;
    asm("{ .reg .u64 t; cvta.to.shared.u64 t, %1; cvt.u32.u64 %0, t; }"
        : "=r"(a) : "l"(p));
    return a;
}
__device__ __forceinline__ void cp_async16(uint32_t saddr, const void* gaddr) {
    asm volatile("cp.async.cg.shared.global [%0], [%1], 16;"
                 :: "r"(saddr), "l"(gaddr));
}
__device__ __forceinline__ void cp_commit() {
    asm volatile("cp.async.commit_group;" ::: "memory");
}
template <int NN>
__device__ __forceinline__ void cp_wait() {
    asm volatile("cp.async.wait_group %0;" :: "n"(NN) : "memory");
}

// ---------------- weight prep: fp32 [K,256]x2 -> fp16 [512][K] ----------------
__global__ void prep_w_kernel(const float* __restrict__ Wl,
                              const float* __restrict__ Wr,
                              __half* __restrict__ Wt, int K) {
    int idx = blockIdx.x * 256 + threadIdx.x;
    if (idx < NLR * K) {
        int n = idx / K, k = idx - n * K;
        float v = (n < HC) ? Wl[k * HC + n] : Wr[k * HC + (n - HC)];
        Wt[idx] = __float2half(v);
    }
}

// ---------------- input projection: h = relu(x @ Win + bin) ----------------
__global__ void input_proj_kernel(const float* __restrict__ x,
                                  const float* __restrict__ Win,
                                  const float* __restrict__ bin) {
    int node = blockIdx.x;
    int c = threadIdx.x;                 // 64 threads
    __shared__ float xs[F_INDIM];
    if (c < F_INDIM) xs[c] = x[node * F_INDIM + c];
    __syncthreads();
    float acc = bin[c];
#pragma unroll
    for (int k = 0; k < F_INDIM; k++)
        acc = fmaf(xs[k], Win[k * C_DIM + c], acc);
    g_hA[node * C_DIM + c] = __float2half(fmaxf(acc, 0.f));
}

// ---------------- CSR build ----------------
__global__ void init_cnt_kernel() {
    int i = blockIdx.x * blockDim.x + threadIdx.x;
    if (i < N_NODES) g_cnt[i] = 1;       // self loop pre-counted
}

__global__ void hist_kernel(const int* __restrict__ dst) {
    int e = blockIdx.x * blockDim.x + threadIdx.x;
    if (e < N_EDGES) atomicAdd(&g_cnt[dst[e]], 1);
}

__global__ void scan1_kernel() {
    __shared__ int sh[256];
    int t = threadIdx.x;
    int i = blockIdx.x * 256 + t;
    int v = (i < N_NODES) ? g_cnt[i] : 0;
    sh[t] = v;
    __syncthreads();
#pragma unroll
    for (int off = 1; off < 256; off <<= 1) {
        int x = (t >= off) ? sh[t - off] : 0;
        __syncthreads();
        sh[t] += x;
        __syncthreads();
    }
    if (i < N_NODES) g_rowptr[i + 1] = sh[t];
    if (t == 255) g_blk[blockIdx.x] = sh[255];
}

__global__ void scan2_kernel(int nblk) {
    __shared__ int sh[128];
    int t = threadIdx.x;
    if (t < nblk) sh[t] = g_blk[t];
    __syncthreads();
    if (t == 0) {
        int run = 0;
        for (int i = 0; i < nblk; i++) { int v = sh[i]; sh[i] = run; run += v; }
    }
    __syncthreads();
    if (t < nblk) g_blk[t] = sh[t];
}

__global__ void scan3_kernel() {
    int i = blockIdx.x * 256 + threadIdx.x;
    if (i < N_NODES) g_rowptr[i + 1] += g_blk[blockIdx.x];
    if (i == 0) g_rowptr[0] = 0;
}

__global__ void init_fill_kernel() {
    int i = blockIdx.x * blockDim.x + threadIdx.x;
    if (i < N_NODES) {
        int p = g_rowptr[i];
        g_col[p] = i;
        g_fill[i] = p + 1;
    }
}

__global__ void scatter_kernel(const int* __restrict__ src,
                               const int* __restrict__ dst) {
    int e = blockIdx.x * blockDim.x + threadIdx.x;
    if (e < N_EDGES) {
        int pos = atomicAdd(&g_fill[dst[e]], 1);
        g_col[pos] = src[e];
    }
}

// ---------------- fp16 mma.sync GEMM, cp.async 3-stage pipeline ----------------
// C[N_PAD, 512] = A[N_PAD, K] @ Wt^T   (Wt: [512][K] fp16, n-major)
// CTA tile 128x128, 8 warps (2m x 4n), warp tile 64x32, BK=32 (2 k16 steps).
#define GBM 128
#define GBN 128
#define GBK 32
#define PITCH 40                             // halfs per row (20 words)
#define A_ST (GBM * PITCH)                   // 5120 halfs
#define B_ST (GBN * PITCH)                   // 5120 halfs
#define STAGE_HALFS (A_ST + B_ST)            // 10240 halfs (20 KB)
#define STG 3
#define GEMM_SMEM (STG * STAGE_HALFS * 2)    // 61440 bytes

__global__ __launch_bounds__(256, 2)
void gemm_f16_kernel(const __half* __restrict__ A,
                     const __half* __restrict__ Wt,
                     __half* __restrict__ Cout, int K) {
    extern __shared__ __half smh[];
    const uint32_t sbase = smem_u32(smh);

    int tid = threadIdx.x;
    int lane = tid & 31, wid = tid >> 5;
    int warp_m = wid >> 2;           // 0..1 (64 rows)
    int warp_n = wid & 3;            // 0..3 (32 cols)
    int fr = lane >> 2, fk = lane & 3;

    int row0 = blockIdx.y * GBM;
    int col0 = blockIdx.x * GBN;

    const int nch = K / GBK;

    auto issue = [&](int ch) {
        uint32_t sA = sbase + (uint32_t)(ch % STG) * (STAGE_HALFS * 2);
        uint32_t sB = sA + A_ST * 2;
        const __half* aG = A + (size_t)row0 * K + ch * GBK;
        const __half* bG = Wt + (size_t)col0 * K + ch * GBK;
#pragma unroll
        for (int i = 0; i < 2; i++) {
            int idx = tid + i * 256;          // 512 16B-chunks for A
            int m = idx >> 2, q = idx & 3;
            cp_async16(sA + (uint32_t)(m * PITCH + q * 8) * 2,
                       aG + (size_t)m * K + q * 8);
        }
#pragma unroll
        for (int i = 0; i < 2; i++) {
            int idx = tid + i * 256;          // 512 16B-chunks for B
            int n = idx >> 2, q = idx & 3;
            cp_async16(sB + (uint32_t)(n * PITCH + q * 8) * 2,
                       bG + (size_t)n * K + q * 8);
        }
        cp_commit();
    };

    for (int p = 0; p < STG - 1 && p < nch; p++) issue(p);

    float acc[4][4][4] = {};

    for (int ch = 0; ch < nch; ch++) {
        if (ch >= nch - 1) cp_wait<0>(); else cp_wait<1>();
        __syncthreads();
        if (ch + STG - 1 < nch) issue(ch + STG - 1);

        const uint32_t* Aw = (const uint32_t*)(smh + (ch % STG) * STAGE_HALFS);
        const uint32_t* Bw = Aw + A_ST / 2;
        const int PW = PITCH / 2;             // 20 words per row
#pragma unroll
        for (int ks = 0; ks < 2; ks++) {
            int kw = ks * 8;
            uint32_t af[4][4];
#pragma unroll
            for (int mt = 0; mt < 4; mt++) {
                const uint32_t* p = Aw + (warp_m * 64 + mt * 16 + fr) * PW + kw + fk;
                af[mt][0] = p[0];
                af[mt][1] = p[8 * PW];
                af[mt][2] = p[4];
                af[mt][3] = p[8 * PW + 4];
            }
            uint32_t bf[4][2];
#pragma unroll
            for (int nt = 0; nt < 4; nt++) {
                const uint32_t* p = Bw + (warp_n * 32 + nt * 8 + fr) * PW + kw + fk;
                bf[nt][0] = p[0];
                bf[nt][1] = p[4];
            }
#pragma unroll
            for (int mt = 0; mt < 4; mt++)
#pragma unroll
                for (int nt = 0; nt < 4; nt++) {
                    float* c = acc[mt][nt];
                    asm volatile(
                        "mma.sync.aligned.m16n8k16.row.col.f32.f16.f16.f32 "
                        "{%0,%1,%2,%3}, {%4,%5,%6,%7}, {%8,%9}, {%0,%1,%2,%3};"
                        : "+f"(c[0]), "+f"(c[1]), "+f"(c[2]), "+f"(c[3])
                        : "r"(af[mt][0]), "r"(af[mt][1]), "r"(af[mt][2]),
                          "r"(af[mt][3]), "r"(bf[nt][0]), "r"(bf[nt][1]));
                }
        }
    }
    __syncthreads();

    // epilogue: fp32 acc -> half2 stores (rows padded: no guards)
#pragma unroll
    for (int mt = 0; mt < 4; mt++) {
#pragma unroll
        for (int nt = 0; nt < 4; nt++) {
            int row = row0 + warp_m * 64 + mt * 16 + fr;
            int col = col0 + warp_n * 32 + nt * 8 + 2 * fk;
            float* c = acc[mt][nt];
            *(__half2*)&Cout[(size_t)row * NLR + col] = __floats2half2_rn(c[0], c[1]);
            *(__half2*)&Cout[(size_t)(row + 8) * NLR + col] = __floats2half2_rn(c[2], c[3]);
        }
    }
}

// ---------------- fused GATv2 edge kernel (warp per node, online softmax) ----
// lane l owns channels [8l, 8l+8); head = l>>3 (64 ch/head)
__global__ void gat_edge_kernel(const __half* __restrict__ xlr,
                                const float* __restrict__ att,
                                const float* __restrict__ bias,
                                const __half* __restrict__ hprev,
                                __half* __restrict__ hout,
                                int residual) {
    int gw = (blockIdx.x * blockDim.x + threadIdx.x) >> 5;
    if (gw >= N_NODES) return;
    int lane = threadIdx.x & 31;
    int cbase = lane * 8;

    float xr_r[8], att_r[8];
    {
        uint4 u = *(const uint4*)&xlr[(size_t)gw * NLR + HC + cbase];
        const __half2* hp = (const __half2*)&u;
#pragma unroll
        for (int j = 0; j < 4; j++) {
            float2 f = __half22float2(hp[j]);
            xr_r[2 * j] = f.x; xr_r[2 * j + 1] = f.y;
        }
        const float4* q = (const float4*)&att[cbase];
        float4 c = q[0], d = q[1];
        att_r[0]=c.x; att_r[1]=c.y; att_r[2]=c.z; att_r[3]=c.w;
        att_r[4]=d.x; att_r[5]=d.y; att_r[6]=d.z; att_r[7]=d.w;
    }

    int e0 = g_rowptr[gw];
    int e1 = g_rowptr[gw + 1];

    float m = -INFINITY, den = 0.f;
    float acc[8] = {0.f,0.f,0.f,0.f,0.f,0.f,0.f,0.f};

    for (int e = e0; e < e1; e++) {
        int s = g_col[e];
        uint4 u = *(const uint4*)&xlr[(size_t)s * NLR + cbase];
        const __half2* hp = (const __half2*)&u;
        float xv[8];
#pragma unroll
        for (int j = 0; j < 4; j++) {
            float2 f = __half22float2(hp[j]);
            xv[2 * j] = f.x; xv[2 * j + 1] = f.y;
        }

        float partial = 0.f;
#pragma unroll
        for (int j = 0; j < 8; j++) {
            float t = xv[j] + xr_r[j];
            t = fmaxf(t, NEG_SLOPE * t);      // leaky_relu
            partial = fmaf(t, att_r[j], partial);
        }
        partial += __shfl_xor_sync(0xffffffffu, partial, 1);
        partial += __shfl_xor_sync(0xffffffffu, partial, 2);
        partial += __shfl_xor_sync(0xffffffffu, partial, 4);
        float logit = partial;

        float m_new = fmaxf(m, logit);
        float scale = __expf(m - m_new);
        float pxe = __expf(logit - m_new);
        den = den * scale + pxe;
#pragma unroll
        for (int j = 0; j < 8; j++)
            acc[j] = fmaf(acc[j], scale, pxe * xv[j]);
        m = m_new;
    }

    float inv = 1.f / (den + 1e-16f);
#pragma unroll
    for (int j = 0; j < 8; j++) {
        float v = fmaf(acc[j], inv, bias[cbase + j]);
        v = (v > 0.f) ? v : (__expf(v) - 1.f);            // ELU
        if (residual) v += __half2float(hprev[gw * HC + cbase + j]);
        hout[gw * HC + cbase + j] = __float2half(v);
    }
}

// ---------------- pooling: partial mean+max, then combine ----------------
__global__ void pool1_kernel(const __half* __restrict__ h) {
    int g = blockIdx.y, ch = blockIdx.x;       // 8 chunks of 125 nodes
    int c = threadIdx.x;                       // 256
    const __half* base = h + ((size_t)g * NODES_PG + ch * 125) * HC;
    float s = 0.f, mx = -INFINITY;
    for (int n = 0; n < 125; n++) {
        float v = __half2float(base[n * HC + c]);
        s += v;
        mx = fmaxf(mx, v);
    }
    float* out = &g_poolP[(size_t)(g * 8 + ch) * 2 * HC];
    out[c] = s;
    out[HC + c] = mx;
}

__global__ void pool2_kernel() {
    int g = blockIdx.x;
    int c = threadIdx.x;                       // 256
    float s = 0.f, mx = -INFINITY;
    for (int ch = 0; ch < 8; ch++) {
        const float* in = &g_poolP[(size_t)(g * 8 + ch) * 2 * HC];
        s += in[c];
        mx = fmaxf(mx, in[HC + c]);
    }
    g_xg[g * (2 * HC) + c]      = s * (1.f / NODES_PG);
    g_xg[g * (2 * HC) + HC + c] = mx;
}

// ---------------- head: out = x_global @ Wout + bout ----------------
__global__ void head_kernel(const float* __restrict__ Wout,
                            const float* __restrict__ bout,
                            float* __restrict__ out) {
    int g = blockIdx.x;
    int o = threadIdx.x;                   // 128
    float acc = bout[o];
    const float* xg = &g_xg[g * 2 * HC];
#pragma unroll 8
    for (int k = 0; k < 2 * HC; k++)
        acc = fmaf(xg[k], Wout[k * OUT_DIM + o], acc);
    out[g * OUT_DIM + o] = acc;
}

// ---------------- launch ----------------
extern "C" void kernel_launch(void* const* d_in, const int* in_sizes, int n_in,
                              void* d_out, int out_size) {
    const float* x    = (const float*)d_in[0];
    const int*   ei   = (const int*)d_in[1];     // [2, E] int32: row0 src, row1 dst
    const float* Win  = (const float*)d_in[3];
    const float* bin  = (const float*)d_in[4];
    const float* Wout = (const float*)d_in[5];
    const float* bout = (const float*)d_in[6];
    const float* Wl[3] = { (const float*)d_in[7],  (const float*)d_in[11], (const float*)d_in[15] };
    const float* Wr[3] = { (const float*)d_in[8],  (const float*)d_in[12], (const float*)d_in[16] };
    const float* At[3] = { (const float*)d_in[9],  (const float*)d_in[13], (const float*)d_in[17] };
    const float* Bi[3] = { (const float*)d_in[10], (const float*)d_in[14], (const float*)d_in[18] };
    float* out = (float*)d_out;

    const int* src = ei;
    const int* dst = ei + N_EDGES;

    __half *hA, *hB, *xlr, *Wt0, *Wt1, *Wt2;
    cudaGetSymbolAddress((void**)&hA,  g_hA);
    cudaGetSymbolAddress((void**)&hB,  g_hB);
    cudaGetSymbolAddress((void**)&xlr, g_xlr);
    cudaGetSymbolAddress((void**)&Wt0, g_Wt0);
    cudaGetSymbolAddress((void**)&Wt1, g_Wt1);
    cudaGetSymbolAddress((void**)&Wt2, g_Wt2);

    cudaFuncSetAttribute(gemm_f16_kernel,
                         cudaFuncAttributeMaxDynamicSharedMemorySize, GEMM_SMEM);

    const int NB = (N_NODES + 255) / 256;   // 79

    // weight prep (fp16, [n][k] transposed)
    prep_w_kernel<<<(NLR * C_DIM + 255) / 256, 256>>>(Wl[0], Wr[0], Wt0, C_DIM);
    prep_w_kernel<<<(NLR * HC + 255) / 256, 256>>>(Wl[1], Wr[1], Wt1, HC);
    prep_w_kernel<<<(NLR * HC + 255) / 256, 256>>>(Wl[2], Wr[2], Wt2, HC);

    // CSR build
    init_cnt_kernel<<<NB, 256>>>();
    hist_kernel<<<(N_EDGES + 255) / 256, 256>>>(dst);
    scan1_kernel<<<NB, 256>>>();
    scan2_kernel<<<1, 128>>>(NB);
    scan3_kernel<<<NB, 256>>>();
    init_fill_kernel<<<NB, 256>>>();
    scatter_kernel<<<(N_EDGES + 255) / 256, 256>>>(src, dst);

    // input projection -> hA [N, 64] fp16
    input_proj_kernel<<<N_NODES, C_DIM>>>(x, Win, bin);

    dim3 ggrid(4, N_PAD / GBM);               // 4 N-tiles x 157 M-tiles
    const int EDGE_THREADS = 256;
    int edge_blocks = (N_NODES * 32 + EDGE_THREADS - 1) / EDGE_THREADS;

    // layer 0: in hA (K=64) -> out hB, no residual
    gemm_f16_kernel<<<ggrid, 256, GEMM_SMEM>>>(hA, Wt0, xlr, C_DIM);
    gat_edge_kernel<<<edge_blocks, EDGE_THREADS>>>(xlr, At[0], Bi[0], hA, hB, 0);

    // layer 1: in hB (K=256) -> out hA, residual hB
    gemm_f16_kernel<<<ggrid, 256, GEMM_SMEM>>>(hB, Wt1, xlr, HC);
    gat_edge_kernel<<<edge_blocks, EDGE_THREADS>>>(xlr, At[1], Bi[1], hB, hA, 1);

    // layer 2: in hA -> out hB, residual hA
    gemm_f16_kernel<<<ggrid, 256, GEMM_SMEM>>>(hA, Wt2, xlr, HC);
    gat_edge_kernel<<<edge_blocks, EDGE_THREADS>>>(xlr, At[2], Bi[2], hA, hB, 1);

    // pooling + head
    pool1_kernel<<<dim3(8, G_GRAPHS), HC>>>(hB);
    pool2_kernel<<<G_GRAPHS, HC>>>();
    head_kernel<<<G_GRAPHS, OUT_DIM>>>(Wout, bout, out);
}

// round 7
// speedup vs baseline: 2.7210x; 1.0851x over previous
#include <cuda_runtime.h>
#include <cuda_fp16.h>
#include <math.h>
#include <stdint.h>

// ---------------- problem constants ----------------
#define N_NODES   20000
#define N_PAD     20096                 // 157 * 128
#define N_EDGES   320000
#define TOT_E     (N_EDGES + N_NODES)   // + self loops
#define F_INDIM   22
#define C_DIM     64
#define H_HEADS   4
#define HC        256
#define NLR       512                   // fused xl|xr row width
#define G_GRAPHS  20
#define NODES_PG  1000
#define OUT_DIM   128
#define NEG_SLOPE 0.2f

#define NBLK_SCAN 79                    // ceil(20000/256)

// ---------------- scratch (static device globals; no allocation) ----------------
__device__ __half g_hA[N_PAD * HC];
__device__ __half g_hB[N_PAD * HC];
__device__ __half g_xlr[N_PAD * NLR];       // [node][xl(256) | xr(256)]
__device__ __half g_Wt0[NLR * C_DIM];       // layer0 weights, [n][k] fp16
__device__ __half g_Wt1[NLR * HC];
__device__ __half g_Wt2[NLR * HC];
__device__ float  g_xg[G_GRAPHS * 2 * HC];
__device__ float  g_poolP[G_GRAPHS * 8 * 2 * HC];
__device__ int    g_cnt[N_NODES];
__device__ int    g_rowptr[N_NODES + 1];
__device__ int    g_fill[N_NODES];
__device__ int    g_col[TOT_E];
__device__ int    g_part[128];              // decoupled-lookback state

// ---------------- helpers ----------------
__device__ __forceinline__ uint32_t smem_u32(const void* p) {
    uint32_t a;
    asm("{ .reg .u64 t; cvta.to.shared.u64 t, %1; cvt.u32.u64 %0, t; }"
        : "=r"(a) : "l"(p));
    return a;
}
__device__ __forceinline__ void cp_async16(uint32_t saddr, const void* gaddr) {
    asm volatile("cp.async.cg.shared.global [%0], [%1], 16;"
                 :: "r"(saddr), "l"(gaddr));
}
__device__ __forceinline__ void cp_commit() {
    asm volatile("cp.async.commit_group;" ::: "memory");
}
template <int NN>
__device__ __forceinline__ void cp_wait() {
    asm volatile("cp.async.wait_group %0;" :: "n"(NN) : "memory");
}

// ---------------- fused prologue ----------------
// blocks [0, 1152)           : weight prep (3 layers -> fp16 [n][k])
// blocks [1152, 1152+5000)   : input projection, 4 nodes / block
// blocks [6152, 6152+79)     : cnt init (+ scan-state zero in first block)
#define PREP_BLOCKS 1152
#define PROJ_BLOCKS 5000
#define CNT_BLOCKS  NBLK_SCAN
#define INIT_BLOCKS (PREP_BLOCKS + PROJ_BLOCKS + CNT_BLOCKS)
#define L0_ELEMS (NLR * C_DIM)              // 32768
#define L12_ELEMS (NLR * HC)                // 131072

__global__ void fused_init_kernel(const float* __restrict__ x,
                                  const float* __restrict__ Win,
                                  const float* __restrict__ bin,
                                  const float* __restrict__ Wl0, const float* __restrict__ Wr0,
                                  const float* __restrict__ Wl1, const float* __restrict__ Wr1,
                                  const float* __restrict__ Wl2, const float* __restrict__ Wr2) {
    int b = blockIdx.x, t = threadIdx.x;
    if (b < PREP_BLOCKS) {
        int idx = b * 256 + t;
        const float* Wl; const float* Wr; __half* Wt; int K; int r;
        if (idx < L0_ELEMS)            { Wl = Wl0; Wr = Wr0; Wt = g_Wt0; K = C_DIM; r = idx; }
        else if (idx < L0_ELEMS + L12_ELEMS) { Wl = Wl1; Wr = Wr1; Wt = g_Wt1; K = HC; r = idx - L0_ELEMS; }
        else                           { Wl = Wl2; Wr = Wr2; Wt = g_Wt2; K = HC; r = idx - L0_ELEMS - L12_ELEMS; }
        int n = r / K, k = r - n * K;
        float v = (n < HC) ? Wl[k * HC + n] : Wr[k * HC + (n - HC)];
        Wt[r] = __float2half(v);
    } else if (b < PREP_BLOCKS + PROJ_BLOCKS) {
        int nb = b - PREP_BLOCKS;
        int ty = t >> 6, c = t & 63;
        int node = nb * 4 + ty;
        __shared__ float xs[4][F_INDIM];
        if (c < F_INDIM) xs[ty][c] = x[node * F_INDIM + c];
        __syncthreads();
        float acc = bin[c];
#pragma unroll
        for (int k = 0; k < F_INDIM; k++)
            acc = fmaf(xs[ty][k], Win[k * C_DIM + c], acc);
        g_hA[node * C_DIM + c] = __float2half(fmaxf(acc, 0.f));
    } else {
        int cb = b - PREP_BLOCKS - PROJ_BLOCKS;
        int i = cb * 256 + t;
        if (i < N_NODES) g_cnt[i] = 1;        // self loop pre-counted
        if (cb == 0 && t < 128) g_part[t] = 0;
    }
}

// ---------------- histogram ----------------
__global__ void hist_kernel(const int* __restrict__ dst) {
    int e4 = blockIdx.x * blockDim.x + threadIdx.x;
    if (e4 < N_EDGES / 4) {
        int4 d = ((const int4*)dst)[e4];
        atomicAdd(&g_cnt[d.x], 1);
        atomicAdd(&g_cnt[d.y], 1);
        atomicAdd(&g_cnt[d.z], 1);
        atomicAdd(&g_cnt[d.w], 1);
    }
}

// ---------------- single-pass scan (decoupled lookback) + fill init --------
#define AFLAG (1 << 30)
#define PFLAG (2 << 30)
#define VMASK 0x3FFFFFFF

__global__ void scanfill_kernel() {
    __shared__ int sh[256];
    __shared__ int s_prefix;
    int b = blockIdx.x, t = threadIdx.x;
    int i = b * 256 + t;
    int v = (i < N_NODES) ? g_cnt[i] : 0;
    sh[t] = v;
    __syncthreads();
#pragma unroll
    for (int off = 1; off < 256; off <<= 1) {
        int u = (t >= off) ? sh[t - off] : 0;
        __syncthreads();
        sh[t] += u;
        __syncthreads();
    }
    int total = sh[255];

    if (b == 0) {
        if (t == 0) {
            s_prefix = 0;
            atomicExch(&g_part[0], PFLAG | total);
        }
    } else {
        if (t == 0) atomicExch(&g_part[b], AFLAG | total);   // publish aggregate
        __syncwarp();
        if (t < 32) {                                        // warp-parallel lookback
            int lane = t;
            int run = 0;
            int j = b - 1;
            for (;;) {
                int idx = j - lane;
                int sval = 0;
                if (idx >= 0) {
                    do { sval = atomicAdd(&g_part[idx], 0); } while (sval == 0);
                }
                unsigned pm = __ballot_sync(0xffffffffu, idx >= 0 && (sval & PFLAG));
                int contrib;
                bool done;
                if (pm) {
                    int lp = __ffs(pm) - 1;       // closest predecessor with P
                    contrib = (lane <= lp) ? (sval & VMASK) : 0;
                    done = true;
                } else {
                    contrib = (idx >= 0) ? (sval & VMASK) : 0;
                    done = false;
                }
#pragma unroll
                for (int o = 16; o; o >>= 1)
                    contrib += __shfl_down_sync(0xffffffffu, contrib, o);
                if (lane == 0) run += contrib;
                if (done) break;
                j -= 32;
            }
            if (lane == 0) {
                s_prefix = run;
                atomicExch(&g_part[b], PFLAG | ((run + total) & VMASK));
            }
        }
    }
    __syncthreads();

    int incl = s_prefix + sh[t];
    int excl = incl - v;
    if (i < N_NODES) {
        g_rowptr[i + 1] = incl;
        g_col[excl] = i;          // self loop first in row
        g_fill[i] = excl + 1;
    }
    if (i == 0) g_rowptr[0] = 0;
}

__global__ void scatter_kernel(const int* __restrict__ src,
                               const int* __restrict__ dst) {
    int e = blockIdx.x * blockDim.x + threadIdx.x;
    if (e < N_EDGES) {
        int pos = atomicAdd(&g_fill[dst[e]], 1);
        g_col[pos] = src[e];
    }
}

// ---------------- fp16 mma.sync GEMM, cp.async 4-stage pipeline ----------------
// C[N_PAD, 512] = A[N_PAD, K] @ Wt^T   (Wt: [512][K] fp16, n-major)
// CTA tile 128x128, 8 warps (2m x 4n), warp tile 64x32, BK=32 (2 k16 steps).
#define GBM 128
#define GBN 128
#define GBK 32
#define PITCH 40                             // halfs per row (20 words)
#define A_ST (GBM * PITCH)                   // 5120 halfs
#define B_ST (GBN * PITCH)                   // 5120 halfs
#define STAGE_HALFS (A_ST + B_ST)            // 10240 halfs (20 KB)
#define STG 4
#define GEMM_SMEM (STG * STAGE_HALFS * 2)    // 81920 bytes

__global__ __launch_bounds__(256, 2)
void gemm_f16_kernel(const __half* __restrict__ A,
                     const __half* __restrict__ Wt,
                     __half* __restrict__ Cout, int K) {
    extern __shared__ __half smh[];
    const uint32_t sbase = smem_u32(smh);

    int tid = threadIdx.x;
    int lane = tid & 31, wid = tid >> 5;
    int warp_m = wid >> 2;           // 0..1 (64 rows)
    int warp_n = wid & 3;            // 0..3 (32 cols)
    int fr = lane >> 2, fk = lane & 3;

    int row0 = blockIdx.y * GBM;
    int col0 = blockIdx.x * GBN;

    const int nch = K / GBK;

    auto issue = [&](int ch) {
        uint32_t sA = sbase + (uint32_t)(ch % STG) * (STAGE_HALFS * 2);
        uint32_t sB = sA + A_ST * 2;
        const __half* aG = A + (size_t)row0 * K + ch * GBK;
        const __half* bG = Wt + (size_t)col0 * K + ch * GBK;
#pragma unroll
        for (int i = 0; i < 2; i++) {
            int idx = tid + i * 256;          // 512 16B-chunks for A
            int m = idx >> 2, q = idx & 3;
            cp_async16(sA + (uint32_t)(m * PITCH + q * 8) * 2,
                       aG + (size_t)m * K + q * 8);
        }
#pragma unroll
        for (int i = 0; i < 2; i++) {
            int idx = tid + i * 256;          // 512 16B-chunks for B
            int n = idx >> 2, q = idx & 3;
            cp_async16(sB + (uint32_t)(n * PITCH + q * 8) * 2,
                       bG + (size_t)n * K + q * 8);
        }
        cp_commit();
    };

    for (int p = 0; p < STG - 1 && p < nch; p++) issue(p);

    float acc[4][4][4] = {};

    for (int ch = 0; ch < nch; ch++) {
        int rem = nch - 1 - ch;               // groups that may stay in flight
        if (rem >= 2) cp_wait<2>(); else if (rem == 1) cp_wait<1>(); else cp_wait<0>();
        __syncthreads();
        if (ch + STG - 1 < nch) issue(ch + STG - 1);

        const uint32_t* Aw = (const uint32_t*)(smh + (ch % STG) * STAGE_HALFS);
        const uint32_t* Bw = Aw + A_ST / 2;
        const int PW = PITCH / 2;             // 20 words per row
#pragma unroll
        for (int ks = 0; ks < 2; ks++) {
            int kw = ks * 8;
            uint32_t af[4][4];
#pragma unroll
            for (int mt = 0; mt < 4; mt++) {
                const uint32_t* p = Aw + (warp_m * 64 + mt * 16 + fr) * PW + kw + fk;
                af[mt][0] = p[0];
                af[mt][1] = p[8 * PW];
                af[mt][2] = p[4];
                af[mt][3] = p[8 * PW + 4];
            }
            uint32_t bf[4][2];
#pragma unroll
            for (int nt = 0; nt < 4; nt++) {
                const uint32_t* p = Bw + (warp_n * 32 + nt * 8 + fr) * PW + kw + fk;
                bf[nt][0] = p[0];
                bf[nt][1] = p[4];
            }
#pragma unroll
            for (int mt = 0; mt < 4; mt++)
#pragma unroll
                for (int nt = 0; nt < 4; nt++) {
                    float* c = acc[mt][nt];
                    asm volatile(
                        "mma.sync.aligned.m16n8k16.row.col.f32.f16.f16.f32 "
                        "{%0,%1,%2,%3}, {%4,%5,%6,%7}, {%8,%9}, {%0,%1,%2,%3};"
                        : "+f"(c[0]), "+f"(c[1]), "+f"(c[2]), "+f"(c[3])
                        : "r"(af[mt][0]), "r"(af[mt][1]), "r"(af[mt][2]),
                          "r"(af[mt][3]), "r"(bf[nt][0]), "r"(bf[nt][1]));
                }
        }
    }
    __syncthreads();

    // epilogue: fp32 acc -> half2 stores (rows padded: no guards)
#pragma unroll
    for (int mt = 0; mt < 4; mt++) {
#pragma unroll
        for (int nt = 0; nt < 4; nt++) {
            int row = row0 + warp_m * 64 + mt * 16 + fr;
            int col = col0 + warp_n * 32 + nt * 8 + 2 * fk;
            float* c = acc[mt][nt];
            *(__half2*)&Cout[(size_t)row * NLR + col] = __floats2half2_rn(c[0], c[1]);
            *(__half2*)&Cout[(size_t)(row + 8) * NLR + col] = __floats2half2_rn(c[2], c[3]);
        }
    }
}

// ---------------- fused GATv2 edge kernel (warp per node, online softmax) ----
// lane l owns channels [8l, 8l+8); head = l>>3 (64 ch/head)
__global__ void gat_edge_kernel(const __half* __restrict__ xlr,
                                const float* __restrict__ att,
                                const float* __restrict__ bias,
                                const __half* __restrict__ hprev,
                                __half* __restrict__ hout,
                                int residual) {
    int gw = (blockIdx.x * blockDim.x + threadIdx.x) >> 5;
    if (gw >= N_NODES) return;
    int lane = threadIdx.x & 31;
    int cbase = lane * 8;

    float xr_r[8], att_r[8];
    {
        uint4 u = *(const uint4*)&xlr[(size_t)gw * NLR + HC + cbase];
        const __half2* hp = (const __half2*)&u;
#pragma unroll
        for (int j = 0; j < 4; j++) {
            float2 f = __half22float2(hp[j]);
            xr_r[2 * j] = f.x; xr_r[2 * j + 1] = f.y;
        }
        const float4* q = (const float4*)&att[cbase];
        float4 c = q[0], d = q[1];
        att_r[0]=c.x; att_r[1]=c.y; att_r[2]=c.z; att_r[3]=c.w;
        att_r[4]=d.x; att_r[5]=d.y; att_r[6]=d.z; att_r[7]=d.w;
    }

    int e0 = g_rowptr[gw];
    int e1 = g_rowptr[gw + 1];

    float m = -INFINITY, den = 0.f;
    float acc[8] = {0.f,0.f,0.f,0.f,0.f,0.f,0.f,0.f};

    // software pipeline: keep the next gather in flight
    int sn = g_col[e0];
    uint4 un = *(const uint4*)&xlr[(size_t)sn * NLR + cbase];

    for (int e = e0; e < e1; e++) {
        uint4 u = un;
        if (e + 1 < e1) {
            int s2 = g_col[e + 1];
            un = *(const uint4*)&xlr[(size_t)s2 * NLR + cbase];
        }
        const __half2* hp = (const __half2*)&u;
        float xv[8];
#pragma unroll
        for (int j = 0; j < 4; j++) {
            float2 f = __half22float2(hp[j]);
            xv[2 * j] = f.x; xv[2 * j + 1] = f.y;
        }

        float partial = 0.f;
#pragma unroll
        for (int j = 0; j < 8; j++) {
            float t = xv[j] + xr_r[j];
            t = fmaxf(t, NEG_SLOPE * t);      // leaky_relu
            partial = fmaf(t, att_r[j], partial);
        }
        partial += __shfl_xor_sync(0xffffffffu, partial, 1);
        partial += __shfl_xor_sync(0xffffffffu, partial, 2);
        partial += __shfl_xor_sync(0xffffffffu, partial, 4);
        float logit = partial;

        float m_new = fmaxf(m, logit);
        float scale = __expf(m - m_new);
        float pxe = __expf(logit - m_new);
        den = den * scale + pxe;
#pragma unroll
        for (int j = 0; j < 8; j++)
            acc[j] = fmaf(acc[j], scale, pxe * xv[j]);
        m = m_new;
    }

    float inv = 1.f / (den + 1e-16f);
#pragma unroll
    for (int j = 0; j < 8; j++) {
        float v = fmaf(acc[j], inv, bias[cbase + j]);
        v = (v > 0.f) ? v : (__expf(v) - 1.f);            // ELU
        if (residual) v += __half2float(hprev[gw * HC + cbase + j]);
        hout[gw * HC + cbase + j] = __float2half(v);
    }
}

// ---------------- pooling: partial mean+max, then combine + head ----------------
__global__ void pool1_kernel(const __half* __restrict__ h) {
    int g = blockIdx.y, ch = blockIdx.x;       // 8 chunks of 125 nodes
    int c = threadIdx.x;                       // 256
    const __half* base = h + ((size_t)g * NODES_PG + ch * 125) * HC;
    float s = 0.f, mx = -INFINITY;
    for (int n = 0; n < 125; n++) {
        float v = __half2float(base[n * HC + c]);
        s += v;
        mx = fmaxf(mx, v);
    }
    float* out = &g_poolP[(size_t)(g * 8 + ch) * 2 * HC];
    out[c] = s;
    out[HC + c] = mx;
}

__global__ void pool2_head_kernel(const float* __restrict__ Wout,
                                  const float* __restrict__ bout,
                                  float* __restrict__ out) {
    __shared__ float xg[2 * HC];
    int g = blockIdx.x;
    int t = threadIdx.x;                       // 256
    float s = 0.f, mx = -INFINITY;
    for (int ch = 0; ch < 8; ch++) {
        const float* in = &g_poolP[(size_t)(g * 8 + ch) * 2 * HC];
        s += in[t];
        mx = fmaxf(mx, in[HC + t]);
    }
    xg[t] = s * (1.f / NODES_PG);
    xg[HC + t] = mx;
    __syncthreads();
    if (t < OUT_DIM) {
        float acc = bout[t];
#pragma unroll 8
        for (int k = 0; k < 2 * HC; k++)
            acc = fmaf(xg[k], Wout[k * OUT_DIM + t], acc);
        out[g * OUT_DIM + t] = acc;
    }
}

// ---------------- launch ----------------
extern "C" void kernel_launch(void* const* d_in, const int* in_sizes, int n_in,
                              void* d_out, int out_size) {
    const float* x    = (const float*)d_in[0];
    const int*   ei   = (const int*)d_in[1];     // [2, E] int32: row0 src, row1 dst
    const float* Win  = (const float*)d_in[3];
    const float* bin  = (const float*)d_in[4];
    const float* Wout = (const float*)d_in[5];
    const float* bout = (const float*)d_in[6];
    const float* Wl[3] = { (const float*)d_in[7],  (const float*)d_in[11], (const float*)d_in[15] };
    const float* Wr[3] = { (const float*)d_in[8],  (const float*)d_in[12], (const float*)d_in[16] };
    const float* At[3] = { (const float*)d_in[9],  (const float*)d_in[13], (const float*)d_in[17] };
    const float* Bi[3] = { (const float*)d_in[10], (const float*)d_in[14], (const float*)d_in[18] };
    float* out = (float*)d_out;

    const int* src = ei;
    const int* dst = ei + N_EDGES;

    __half *hA, *hB, *xlr, *Wt0, *Wt1, *Wt2;
    cudaGetSymbolAddress((void**)&hA,  g_hA);
    cudaGetSymbolAddress((void**)&hB,  g_hB);
    cudaGetSymbolAddress((void**)&xlr, g_xlr);
    cudaGetSymbolAddress((void**)&Wt0, g_Wt0);
    cudaGetSymbolAddress((void**)&Wt1, g_Wt1);
    cudaGetSymbolAddress((void**)&Wt2, g_Wt2);

    cudaFuncSetAttribute(gemm_f16_kernel,
                         cudaFuncAttributeMaxDynamicSharedMemorySize, GEMM_SMEM);

    // fused prologue: weight prep + input proj + cnt init + scan-state zero
    fused_init_kernel<<<INIT_BLOCKS, 256>>>(x, Win, bin,
                                            Wl[0], Wr[0], Wl[1], Wr[1], Wl[2], Wr[2]);

    // CSR build: histogram -> single-pass scan/fill -> scatter
    hist_kernel<<<(N_EDGES / 4 + 255) / 256, 256>>>(dst);
    scanfill_kernel<<<NBLK_SCAN, 256>>>();
    scatter_kernel<<<(N_EDGES + 255) / 256, 256>>>(src, dst);

    dim3 ggrid(4, N_PAD / GBM);               // 4 N-tiles x 157 M-tiles
    const int EDGE_THREADS = 256;
    int edge_blocks = (N_NODES * 32 + EDGE_THREADS - 1) / EDGE_THREADS;

    // layer 0: in hA (K=64) -> out hB, no residual
    gemm_f16_kernel<<<ggrid, 256, GEMM_SMEM>>>(hA, Wt0, xlr, C_DIM);
    gat_edge_kernel<<<edge_blocks, EDGE_THREADS>>>(xlr, At[0], Bi[0], hA, hB, 0);

    // layer 1: in hB (K=256) -> out hA, residual hB
    gemm_f16_kernel<<<ggrid, 256, GEMM_SMEM>>>(hB, Wt1, xlr, HC);
    gat_edge_kernel<<<edge_blocks, EDGE_THREADS>>>(xlr, At[1], Bi[1], hB, hA, 1);

    // layer 2: in hA -> out hB, residual hA
    gemm_f16_kernel<<<ggrid, 256, GEMM_SMEM>>>(hA, Wt2, xlr, HC);
    gat_edge_kernel<<<edge_blocks, EDGE_THREADS>>>(xlr, At[2], Bi[2], hA, hB, 1);

    // pooling + head
    pool1_kernel<<<dim3(8, G_GRAPHS), HC>>>(hB);
    pool2_head_kernel<<<G_GRAPHS, HC>>>(Wout, bout, out);
}

// round 9
// speedup vs baseline: 2.7651x; 1.0162x over previous
#include <cuda_runtime.h>
#include <cuda_fp16.h>
#include <math.h>
#include <stdint.h>

// ---------------- problem constants ----------------
#define N_NODES   20000
#define N_PAD     20096                 // 157 * 128
#define N_EDGES   320000
#define TOT_E     (N_EDGES + N_NODES)   // + self loops
#define F_INDIM   22
#define C_DIM     64
#define H_HEADS   4
#define HC        256
#define NLR       512                   // fused xl|xr row width
#define G_GRAPHS  20
#define NODES_PG  1000
#define OUT_DIM   128
#define NEG_SLOPE 0.2f

#define NBLK_SCAN 79                    // ceil(20000/256)

// ---------------- scratch (static device globals; no allocation) ----------------
__device__ __half g_hA[N_PAD * HC];
__device__ __half g_hB[N_PAD * HC];
__device__ __half g_xlr[N_PAD * NLR];       // [node][xl(256) | xr(256)]
__device__ __half g_Wt0[NLR * C_DIM];       // layer0 weights, [n][k] fp16
__device__ __half g_Wt1[NLR * HC];
__device__ __half g_Wt2[NLR * HC];
__device__ float  g_xg[G_GRAPHS * 2 * HC];
__device__ float  g_poolP[G_GRAPHS * 8 * 2 * HC];
__device__ int    g_cnt[N_NODES];
__device__ int    g_rowptr[N_NODES + 1];
__device__ int    g_fill[N_NODES];
__device__ int    g_col[TOT_E];
__device__ int    g_part[128];              // decoupled-lookback state

// ---------------- helpers ----------------
__device__ __forceinline__ uint32_t smem_u32(const void* p) {
    uint32_t a;
    asm("{ .reg .u64 t; cvta.to.shared.u64 t, %1; cvt.u32.u64 %0, t; }"
        : "=r"(a) : "l"(p));
    return a;
}
__device__ __forceinline__ void cp_async16(uint32_t saddr, const void* gaddr) {
    asm volatile("cp.async.cg.shared.global [%0], [%1], 16;"
                 :: "r"(saddr), "l"(gaddr));
}
__device__ __forceinline__ void cp_commit() {
    asm volatile("cp.async.commit_group;" ::: "memory");
}
template <int NN>
__device__ __forceinline__ void cp_wait() {
    asm volatile("cp.async.wait_group %0;" :: "n"(NN) : "memory");
}

// ---------------- fused prologue ----------------
#define PREP_BLOCKS 1152
#define PROJ_BLOCKS 5000
#define CNT_BLOCKS  NBLK_SCAN
#define INIT_BLOCKS (PREP_BLOCKS + PROJ_BLOCKS + CNT_BLOCKS)
#define L0_ELEMS (NLR * C_DIM)              // 32768
#define L12_ELEMS (NLR * HC)                // 131072

__global__ void fused_init_kernel(const float* __restrict__ x,
                                  const float* __restrict__ Win,
                                  const float* __restrict__ bin,
                                  const float* __restrict__ Wl0, const float* __restrict__ Wr0,
                                  const float* __restrict__ Wl1, const float* __restrict__ Wr1,
                                  const float* __restrict__ Wl2, const float* __restrict__ Wr2) {
    int b = blockIdx.x, t = threadIdx.x;
    if (b < PREP_BLOCKS) {
        int idx = b * 256 + t;
        const float* Wl; const float* Wr; __half* Wt; int K; int r;
        if (idx < L0_ELEMS)            { Wl = Wl0; Wr = Wr0; Wt = g_Wt0; K = C_DIM; r = idx; }
        else if (idx < L0_ELEMS + L12_ELEMS) { Wl = Wl1; Wr = Wr1; Wt = g_Wt1; K = HC; r = idx - L0_ELEMS; }
        else                           { Wl = Wl2; Wr = Wr2; Wt = g_Wt2; K = HC; r = idx - L0_ELEMS - L12_ELEMS; }
        int n = r / K, k = r - n * K;
        float v = (n < HC) ? Wl[k * HC + n] : Wr[k * HC + (n - HC)];
        Wt[r] = __float2half(v);
    } else if (b < PREP_BLOCKS + PROJ_BLOCKS) {
        int nb = b - PREP_BLOCKS;
        int ty = t >> 6, c = t & 63;
        int node = nb * 4 + ty;
        __shared__ float xs[4][F_INDIM];
        if (c < F_INDIM) xs[ty][c] = x[node * F_INDIM + c];
        __syncthreads();
        float acc = bin[c];
#pragma unroll
        for (int k = 0; k < F_INDIM; k++)
            acc = fmaf(xs[ty][k], Win[k * C_DIM + c], acc);
        g_hA[node * C_DIM + c] = __float2half(fmaxf(acc, 0.f));
    } else {
        int cb = b - PREP_BLOCKS - PROJ_BLOCKS;
        int i = cb * 256 + t;
        if (i < N_NODES) g_cnt[i] = 1;        // self loop pre-counted
        if (cb == 0 && t < 128) g_part[t] = 0;
    }
}

// ---------------- histogram ----------------
__global__ void hist_kernel(const int* __restrict__ dst) {
    int e4 = blockIdx.x * blockDim.x + threadIdx.x;
    if (e4 < N_EDGES / 4) {
        int4 d = ((const int4*)dst)[e4];
        atomicAdd(&g_cnt[d.x], 1);
        atomicAdd(&g_cnt[d.y], 1);
        atomicAdd(&g_cnt[d.z], 1);
        atomicAdd(&g_cnt[d.w], 1);
    }
}

// ---------------- single-pass scan (decoupled lookback) + fill init --------
#define AFLAG (1 << 30)
#define PFLAG (2 << 30)
#define VMASK 0x3FFFFFFF

__global__ void scanfill_kernel() {
    __shared__ int sh[256];
    __shared__ int s_prefix;
    int b = blockIdx.x, t = threadIdx.x;
    int i = b * 256 + t;
    int v = (i < N_NODES) ? g_cnt[i] : 0;
    sh[t] = v;
    __syncthreads();
#pragma unroll
    for (int off = 1; off < 256; off <<= 1) {
        int u = (t >= off) ? sh[t - off] : 0;
        __syncthreads();
        sh[t] += u;
        __syncthreads();
    }
    int total = sh[255];

    if (b == 0) {
        if (t == 0) {
            s_prefix = 0;
            atomicExch(&g_part[0], PFLAG | total);
        }
    } else {
        if (t == 0) atomicExch(&g_part[b], AFLAG | total);   // publish aggregate
        __syncwarp();
        if (t < 32) {                                        // warp-parallel lookback
            int lane = t;
            int run = 0;
            int j = b - 1;
            for (;;) {
                int idx = j - lane;
                int sval = 0;
                if (idx >= 0) {
                    do { sval = atomicAdd(&g_part[idx], 0); } while (sval == 0);
                }
                unsigned pm = __ballot_sync(0xffffffffu, idx >= 0 && (sval & PFLAG));
                int contrib;
                bool done;
                if (pm) {
                    int lp = __ffs(pm) - 1;       // closest predecessor with P
                    contrib = (lane <= lp) ? (sval & VMASK) : 0;
                    done = true;
                } else {
                    contrib = (idx >= 0) ? (sval & VMASK) : 0;
                    done = false;
                }
#pragma unroll
                for (int o = 16; o; o >>= 1)
                    contrib += __shfl_down_sync(0xffffffffu, contrib, o);
                if (lane == 0) run += contrib;
                if (done) break;
                j -= 32;
            }
            if (lane == 0) {
                s_prefix = run;
                atomicExch(&g_part[b], PFLAG | ((run + total) & VMASK));
            }
        }
    }
    __syncthreads();

    int incl = s_prefix + sh[t];
    int excl = incl - v;
    if (i < N_NODES) {
        g_rowptr[i + 1] = incl;
        g_col[excl] = i;          // self loop first in row
        g_fill[i] = excl + 1;
    }
    if (i == 0) g_rowptr[0] = 0;
}

// ---------------- scatter: 4 edges/thread for MLP ----------------
__global__ void scatter_kernel(const int* __restrict__ src,
                               const int* __restrict__ dst) {
    int e4 = blockIdx.x * blockDim.x + threadIdx.x;
    if (e4 < N_EDGES / 4) {
        int4 s = ((const int4*)src)[e4];
        int4 d = ((const int4*)dst)[e4];
        int p0 = atomicAdd(&g_fill[d.x], 1);
        int p1 = atomicAdd(&g_fill[d.y], 1);
        int p2 = atomicAdd(&g_fill[d.z], 1);
        int p3 = atomicAdd(&g_fill[d.w], 1);
        g_col[p0] = s.x;
        g_col[p1] = s.y;
        g_col[p2] = s.z;
        g_col[p3] = s.w;
    }
}

// ---------------- fp16 mma.sync GEMM, cp.async 4-stage, ldmatrix frags ------
// C[N_PAD, 512] = A[N_PAD, K] @ Wt^T   (Wt: [512][K] fp16, n-major)
// CTA tile 128x128, 8 warps (2m x 4n), warp tile 64x32, BK=32 (2 k16 steps).
// PITCH=40 halfs (80B rows): 8 ldmatrix row addrs hit disjoint bank quads.
#define GBM 128
#define GBN 128
#define GBK 32
#define PITCH 40                             // halfs per row
#define A_ST (GBM * PITCH)                   // 5120 halfs
#define B_ST (GBN * PITCH)                   // 5120 halfs
#define STAGE_HALFS (A_ST + B_ST)            // 10240 halfs (20 KB)
#define STG 4
#define GEMM_SMEM (STG * STAGE_HALFS * 2)    // 81920 bytes

__global__ __launch_bounds__(256, 2)
void gemm_f16_kernel(const __half* __restrict__ A,
                     const __half* __restrict__ Wt,
                     __half* __restrict__ Cout, int K) {
    extern __shared__ __half smh[];
    const uint32_t sbase = smem_u32(smh);

    int tid = threadIdx.x;
    int lane = tid & 31, wid = tid >> 5;
    int warp_m = wid >> 2;           // 0..1 (64 rows)
    int warp_n = wid & 3;            // 0..3 (32 cols)
    int fr = lane >> 2, fk = lane & 3;

    int row0 = blockIdx.y * GBM;
    int col0 = blockIdx.x * GBN;

    const int nch = K / GBK;

    // ldmatrix per-thread coordinates
    int aRow = warp_m * 64 + (lane & 15);
    int aColH = (lane >> 4) * 8;                               // halfs
    int bRow = warp_n * 32 + ((lane >> 4) * 8) + (lane & 7);
    int bColH = ((lane >> 3) & 1) * 8;                         // halfs

    auto issue = [&](int ch) {
        uint32_t sA = sbase + (uint32_t)(ch % STG) * (STAGE_HALFS * 2);
        uint32_t sB = sA + A_ST * 2;
        const __half* aG = A + (size_t)row0 * K + ch * GBK;
        const __half* bG = Wt + (size_t)col0 * K + ch * GBK;
#pragma unroll
        for (int i = 0; i < 2; i++) {
            int idx = tid + i * 256;          // 512 16B-chunks for A
            int m = idx >> 2, q = idx & 3;
            cp_async16(sA + (uint32_t)(m * PITCH + q * 8) * 2,
                       aG + (size_t)m * K + q * 8);
        }
#pragma unroll
        for (int i = 0; i < 2; i++) {
            int idx = tid + i * 256;          // 512 16B-chunks for B
            int n = idx >> 2, q = idx & 3;
            cp_async16(sB + (uint32_t)(n * PITCH + q * 8) * 2,
                       bG + (size_t)n * K + q * 8);
        }
        cp_commit();
    };

    for (int p = 0; p < STG - 1 && p < nch; p++) issue(p);

    float acc[4][4][4] = {};

    for (int ch = 0; ch < nch; ch++) {
        int rem = nch - 1 - ch;
        if (rem >= 2) cp_wait<2>(); else if (rem == 1) cp_wait<1>(); else cp_wait<0>();
        __syncthreads();
        if (ch + STG - 1 < nch) issue(ch + STG - 1);

        uint32_t stA = sbase + (uint32_t)(ch % STG) * (STAGE_HALFS * 2);
        uint32_t stB = stA + A_ST * 2;
#pragma unroll
        for (int ks = 0; ks < 2; ks++) {
            uint32_t af[4][4];
#pragma unroll
            for (int mt = 0; mt < 4; mt++) {
                uint32_t ad = stA + (uint32_t)((aRow + mt * 16) * PITCH + aColH + ks * 16) * 2;
                asm volatile(
                    "ldmatrix.sync.aligned.m8n8.x4.shared.b16 {%0,%1,%2,%3}, [%4];"
                    : "=r"(af[mt][0]), "=r"(af[mt][1]),
                      "=r"(af[mt][2]), "=r"(af[mt][3]) : "r"(ad));
            }
            uint32_t bf[4][2];
#pragma unroll
            for (int p = 0; p < 2; p++) {
                uint32_t bd = stB + (uint32_t)((bRow + p * 16) * PITCH + bColH + ks * 16) * 2;
                uint32_t r0, r1, r2, r3;
                asm volatile(
                    "ldmatrix.sync.aligned.m8n8.x4.shared.b16 {%0,%1,%2,%3}, [%4];"
                    : "=r"(r0), "=r"(r1), "=r"(r2), "=r"(r3) : "r"(bd));
                bf[2 * p][0] = r0; bf[2 * p][1] = r1;
                bf[2 * p + 1][0] = r2; bf[2 * p + 1][1] = r3;
            }
#pragma unroll
            for (int mt = 0; mt < 4; mt++)
#pragma unroll
                for (int nt = 0; nt < 4; nt++) {
                    float* c = acc[mt][nt];
                    asm volatile(
                        "mma.sync.aligned.m16n8k16.row.col.f32.f16.f16.f32 "
                        "{%0,%1,%2,%3}, {%4,%5,%6,%7}, {%8,%9}, {%0,%1,%2,%3};"
                        : "+f"(c[0]), "+f"(c[1]), "+f"(c[2]), "+f"(c[3])
                        : "r"(af[mt][0]), "r"(af[mt][1]), "r"(af[mt][2]),
                          "r"(af[mt][3]), "r"(bf[nt][0]), "r"(bf[nt][1]));
                }
        }
    }
    __syncthreads();

    // epilogue: fp32 acc -> half2 stores (rows padded: no guards)
#pragma unroll
    for (int mt = 0; mt < 4; mt++) {
#pragma unroll
        for (int nt = 0; nt < 4; nt++) {
            int row = row0 + warp_m * 64 + mt * 16 + fr;
            int col = col0 + warp_n * 32 + nt * 8 + 2 * fk;
            float* c = acc[mt][nt];
            *(__half2*)&Cout[(size_t)row * NLR + col] = __floats2half2_rn(c[0], c[1]);
            *(__half2*)&Cout[(size_t)(row + 8) * NLR + col] = __floats2half2_rn(c[2], c[3]);
        }
    }
}

// ---------------- fused GATv2 edge kernel (warp per node, online softmax) ----
// lane l owns channels [8l, 8l+8); head = l>>3 (64 ch/head); MLP-4 gathers
__global__ void gat_edge_kernel(const __half* __restrict__ xlr,
                                const float* __restrict__ att,
                                const float* __restrict__ bias,
                                const __half* __restrict__ hprev,
                                __half* __restrict__ hout,
                                int residual) {
    int gw = (blockIdx.x * blockDim.x + threadIdx.x) >> 5;
    if (gw >= N_NODES) return;
    int lane = threadIdx.x & 31;
    int cbase = lane * 8;

    float xr_r[8], att_r[8];
    {
        uint4 u = *(const uint4*)&xlr[(size_t)gw * NLR + HC + cbase];
        const __half2* hp = (const __half2*)&u;
#pragma unroll
        for (int j = 0; j < 4; j++) {
            float2 f = __half22float2(hp[j]);
            xr_r[2 * j] = f.x; xr_r[2 * j + 1] = f.y;
        }
        const float4* q = (const float4*)&att[cbase];
        float4 c = q[0], d = q[1];
        att_r[0]=c.x; att_r[1]=c.y; att_r[2]=c.z; att_r[3]=c.w;
        att_r[4]=d.x; att_r[5]=d.y; att_r[6]=d.z; att_r[7]=d.w;
    }

    int e0 = g_rowptr[gw];
    int e1 = g_rowptr[gw + 1];

    float m = -INFINITY, den = 0.f;
    float acc[8] = {0.f,0.f,0.f,0.f,0.f,0.f,0.f,0.f};

    for (int base = e0; base < e1; base += 4) {
        int lim = e1 - base; if (lim > 4) lim = 4;
        int idx[4];
        uint4 u[4];
#pragma unroll
        for (int d = 0; d < 4; d++)
            if (d < lim) idx[d] = g_col[base + d];
#pragma unroll
        for (int d = 0; d < 4; d++)
            if (d < lim) u[d] = *(const uint4*)&xlr[(size_t)idx[d] * NLR + cbase];

#pragma unroll
        for (int d = 0; d < 4; d++) {
            if (d >= lim) break;
            const __half2* hp = (const __half2*)&u[d];
            float xv[8];
#pragma unroll
            for (int j = 0; j < 4; j++) {
                float2 f = __half22float2(hp[j]);
                xv[2 * j] = f.x; xv[2 * j + 1] = f.y;
            }

            float partial = 0.f;
#pragma unroll
            for (int j = 0; j < 8; j++) {
                float t = xv[j] + xr_r[j];
                t = fmaxf(t, NEG_SLOPE * t);      // leaky_relu
                partial = fmaf(t, att_r[j], partial);
            }
            partial += __shfl_xor_sync(0xffffffffu, partial, 1);
            partial += __shfl_xor_sync(0xffffffffu, partial, 2);
            partial += __shfl_xor_sync(0xffffffffu, partial, 4);
            float logit = partial;

            float m_new = fmaxf(m, logit);
            float scale = __expf(m - m_new);
            float pxe = __expf(logit - m_new);
            den = den * scale + pxe;
#pragma unroll
            for (int j = 0; j < 8; j++)
                acc[j] = fmaf(acc[j], scale, pxe * xv[j]);
            m = m_new;
        }
    }

    float inv = 1.f / (den + 1e-16f);
#pragma unroll
    for (int j = 0; j < 8; j++) {
        float v = fmaf(acc[j], inv, bias[cbase + j]);
        v = (v > 0.f) ? v : (__expf(v) - 1.f);            // ELU
        if (residual) v += __half2float(hprev[gw * HC + cbase + j]);
        hout[gw * HC + cbase + j] = __float2half(v);
    }
}

// ---------------- pooling: partial mean+max, then combine + head ----------------
__global__ void pool1_kernel(const __half* __restrict__ h) {
    int g = blockIdx.y, ch = blockIdx.x;       // 8 chunks of 125 nodes
    int c = threadIdx.x;                       // 256
    const __half* base = h + ((size_t)g * NODES_PG + ch * 125) * HC;
    float s = 0.f, mx = -INFINITY;
    for (int n = 0; n < 125; n++) {
        float v = __half2float(base[n * HC + c]);
        s += v;
        mx = fmaxf(mx, v);
    }
    float* out = &g_poolP[(size_t)(g * 8 + ch) * 2 * HC];
    out[c] = s;
    out[HC + c] = mx;
}

__global__ void pool2_head_kernel(const float* __restrict__ Wout,
                                  const float* __restrict__ bout,
                                  float* __restrict__ out) {
    __shared__ float xg[2 * HC];
    int g = blockIdx.x;
    int t = threadIdx.x;                       // 256
    float s = 0.f, mx = -INFINITY;
    for (int ch = 0; ch < 8; ch++) {
        const float* in = &g_poolP[(size_t)(g * 8 + ch) * 2 * HC];
        s += in[t];
        mx = fmaxf(mx, in[HC + t]);
    }
    xg[t] = s * (1.f / NODES_PG);
    xg[HC + t] = mx;
    __syncthreads();
    if (t < OUT_DIM) {
        float acc = bout[t];
#pragma unroll 8
        for (int k = 0; k < 2 * HC; k++)
            acc = fmaf(xg[k], Wout[k * OUT_DIM + t], acc);
        out[g * OUT_DIM + t] = acc;
    }
}

// ---------------- launch ----------------
extern "C" void kernel_launch(void* const* d_in, const int* in_sizes, int n_in,
                              void* d_out, int out_size) {
    const float* x    = (const float*)d_in[0];
    const int*   ei   = (const int*)d_in[1];     // [2, E] int32: row0 src, row1 dst
    const float* Win  = (const float*)d_in[3];
    const float* bin  = (const float*)d_in[4];
    const float* Wout = (const float*)d_in[5];
    const float* bout = (const float*)d_in[6];
    const float* Wl[3] = { (const float*)d_in[7],  (const float*)d_in[11], (const float*)d_in[15] };
    const float* Wr[3] = { (const float*)d_in[8],  (const float*)d_in[12], (const float*)d_in[16] };
    const float* At[3] = { (const float*)d_in[9],  (const float*)d_in[13], (const float*)d_in[17] };
    const float* Bi[3] = { (const float*)d_in[10], (const float*)d_in[14], (const float*)d_in[18] };
    float* out = (float*)d_out;

    const int* src = ei;
    const int* dst = ei + N_EDGES;

    __half *hA, *hB, *xlr, *Wt0, *Wt1, *Wt2;
    cudaGetSymbolAddress((void**)&hA,  g_hA);
    cudaGetSymbolAddress((void**)&hB,  g_hB);
    cudaGetSymbolAddress((void**)&xlr, g_xlr);
    cudaGetSymbolAddress((void**)&Wt0, g_Wt0);
    cudaGetSymbolAddress((void**)&Wt1, g_Wt1);
    cudaGetSymbolAddress((void**)&Wt2, g_Wt2);

    cudaFuncSetAttribute(gemm_f16_kernel,
                         cudaFuncAttributeMaxDynamicSharedMemorySize, GEMM_SMEM);

    // fused prologue: weight prep + input proj + cnt init + scan-state zero
    fused_init_kernel<<<INIT_BLOCKS, 256>>>(x, Win, bin,
                                            Wl[0], Wr[0], Wl[1], Wr[1], Wl[2], Wr[2]);

    // CSR build: histogram -> single-pass scan/fill -> scatter
    hist_kernel<<<(N_EDGES / 4 + 255) / 256, 256>>>(dst);
    scanfill_kernel<<<NBLK_SCAN, 256>>>();
    scatter_kernel<<<(N_EDGES / 4 + 255) / 256, 256>>>(src, dst);

    dim3 ggrid(4, N_PAD / GBM);               // 4 N-tiles x 157 M-tiles
    const int EDGE_THREADS = 256;
    int edge_blocks = (N_NODES * 32 + EDGE_THREADS - 1) / EDGE_THREADS;

    // layer 0: in hA (K=64) -> out hB, no residual
    gemm_f16_kernel<<<ggrid, 256, GEMM_SMEM>>>(hA, Wt0, xlr, C_DIM);
    gat_edge_kernel<<<edge_blocks, EDGE_THREADS>>>(xlr, At[0], Bi[0], hA, hB, 0);

    // layer 1: in hB (K=256) -> out hA, residual hB
    gemm_f16_kernel<<<ggrid, 256, GEMM_SMEM>>>(hB, Wt1, xlr, HC);
    gat_edge_kernel<<<edge_blocks, EDGE_THREADS>>>(xlr, At[1], Bi[1], hB, hA, 1);

    // layer 2: in hA -> out hB, residual hA
    gemm_f16_kernel<<<ggrid, 256, GEMM_SMEM>>>(hA, Wt2, xlr, HC);
    gat_edge_kernel<<<edge_blocks, EDGE_THREADS>>>(xlr, At[2], Bi[2], hA, hB, 1);

    // pooling + head
    pool1_kernel<<<dim3(8, G_GRAPHS), HC>>>(hB);
    pool2_head_kernel<<<G_GRAPHS, HC>>>(Wout, bout, out);
}

// round 10
// speedup vs baseline: 2.8184x; 1.0193x over previous
#include <cuda_runtime.h>
#include <cuda_fp16.h>
#include <math.h>
#include <stdint.h>

// ---------------- problem constants ----------------
#define N_NODES   20000
#define N_PAD     20096                 // 157 * 128
#define N_EDGES   320000
#define TOT_E     (N_EDGES + N_NODES)   // + self loops
#define F_INDIM   22
#define C_DIM     64
#define H_HEADS   4
#define HC        256
#define NLR       512                   // fused xl|xr row width
#define G_GRAPHS  20
#define NODES_PG  1000
#define OUT_DIM   128
#define NEG_SLOPE 0.2f

#define NBLK_SCAN 79                    // ceil(20000/256)

// ---------------- scratch (static device globals; no allocation) ----------------
__device__ __half g_hA[N_PAD * HC];
__device__ __half g_hB[N_PAD * HC];
__device__ __half g_xlr[N_PAD * NLR];       // [node][xl(256) | xr(256)]
__device__ __half g_Wt0[NLR * C_DIM];       // layer0 weights, [n][k] fp16
__device__ __half g_Wt1[NLR * HC];
__device__ __half g_Wt2[NLR * HC];
__device__ float  g_xg[G_GRAPHS * 2 * HC];
__device__ float  g_poolP[G_GRAPHS * 8 * 2 * HC];
__device__ int    g_cnt[N_NODES];
__device__ int    g_rowptr[N_NODES + 1];
__device__ int    g_fill[N_NODES];
__device__ int    g_col[TOT_E];
__device__ int    g_part[128];              // decoupled-lookback state

// ---------------- helpers ----------------
__device__ __forceinline__ uint32_t smem_u32(const void* p) {
    uint32_t a;
    asm("{ .reg .u64 t; cvta.to.shared.u64 t, %1; cvt.u32.u64 %0, t; }"
        : "=r"(a) : "l"(p));
    return a;
}
__device__ __forceinline__ void cp_async16(uint32_t saddr, const void* gaddr) {
    asm volatile("cp.async.cg.shared.global [%0], [%1], 16;"
                 :: "r"(saddr), "l"(gaddr));
}
__device__ __forceinline__ void cp_commit() {
    asm volatile("cp.async.commit_group;" ::: "memory");
}
template <int NN>
__device__ __forceinline__ void cp_wait() {
    asm volatile("cp.async.wait_group %0;" :: "n"(NN) : "memory");
}

// ---------------- fused prologue (weights + input proj only) ----------------
#define PREP_BLOCKS 1152
#define PROJ_BLOCKS 5000
#define INIT_BLOCKS (PREP_BLOCKS + PROJ_BLOCKS)
#define L0_ELEMS (NLR * C_DIM)              // 32768
#define L12_ELEMS (NLR * HC)                // 131072

__global__ void fused_init_kernel(const float* __restrict__ x,
                                  const float* __restrict__ Win,
                                  const float* __restrict__ bin,
                                  const float* __restrict__ Wl0, const float* __restrict__ Wr0,
                                  const float* __restrict__ Wl1, const float* __restrict__ Wr1,
                                  const float* __restrict__ Wl2, const float* __restrict__ Wr2) {
    int b = blockIdx.x, t = threadIdx.x;
    if (b < PREP_BLOCKS) {
        int idx = b * 256 + t;
        const float* Wl; const float* Wr; __half* Wt; int K; int r;
        if (idx < L0_ELEMS)            { Wl = Wl0; Wr = Wr0; Wt = g_Wt0; K = C_DIM; r = idx; }
        else if (idx < L0_ELEMS + L12_ELEMS) { Wl = Wl1; Wr = Wr1; Wt = g_Wt1; K = HC; r = idx - L0_ELEMS; }
        else                           { Wl = Wl2; Wr = Wr2; Wt = g_Wt2; K = HC; r = idx - L0_ELEMS - L12_ELEMS; }
        int n = r / K, k = r - n * K;
        float v = (n < HC) ? Wl[k * HC + n] : Wr[k * HC + (n - HC)];
        Wt[r] = __float2half(v);
    } else {
        int nb = b - PREP_BLOCKS;
        int ty = t >> 6, c = t & 63;
        int node = nb * 4 + ty;
        __shared__ float xs[4][F_INDIM];
        if (c < F_INDIM) xs[ty][c] = x[node * F_INDIM + c];
        __syncthreads();
        float acc = bin[c];
#pragma unroll
        for (int k = 0; k < F_INDIM; k++)
            acc = fmaf(xs[ty][k], Win[k * C_DIM + c], acc);
        g_hA[node * C_DIM + c] = __float2half(fmaxf(acc, 0.f));
    }
}

// ---------------- CSR branch (side stream) ----------------
__global__ void initcnt_kernel() {
    int i = blockIdx.x * 256 + threadIdx.x;
    if (i < N_NODES) g_cnt[i] = 1;          // self loop pre-counted
    if (blockIdx.x == 0 && threadIdx.x < 128) g_part[threadIdx.x] = 0;
}

__global__ void hist_kernel(const int* __restrict__ dst) {
    int e4 = blockIdx.x * blockDim.x + threadIdx.x;
    if (e4 < N_EDGES / 4) {
        int4 d = ((const int4*)dst)[e4];
        atomicAdd(&g_cnt[d.x], 1);
        atomicAdd(&g_cnt[d.y], 1);
        atomicAdd(&g_cnt[d.z], 1);
        atomicAdd(&g_cnt[d.w], 1);
    }
}

// ---------------- single-pass scan (decoupled lookback) + fill init --------
#define AFLAG (1 << 30)
#define PFLAG (2 << 30)
#define VMASK 0x3FFFFFFF

__global__ void scanfill_kernel() {
    __shared__ int sh[256];
    __shared__ int s_prefix;
    int b = blockIdx.x, t = threadIdx.x;
    int i = b * 256 + t;
    int v = (i < N_NODES) ? g_cnt[i] : 0;
    sh[t] = v;
    __syncthreads();
#pragma unroll
    for (int off = 1; off < 256; off <<= 1) {
        int u = (t >= off) ? sh[t - off] : 0;
        __syncthreads();
        sh[t] += u;
        __syncthreads();
    }
    int total = sh[255];

    if (b == 0) {
        if (t == 0) {
            s_prefix = 0;
            atomicExch(&g_part[0], PFLAG | total);
        }
    } else {
        if (t == 0) atomicExch(&g_part[b], AFLAG | total);   // publish aggregate
        __syncwarp();
        if (t < 32) {                                        // warp-parallel lookback
            int lane = t;
            int run = 0;
            int j = b - 1;
            for (;;) {
                int idx = j - lane;
                int sval = 0;
                if (idx >= 0) {
                    do { sval = atomicAdd(&g_part[idx], 0); } while (sval == 0);
                }
                unsigned pm = __ballot_sync(0xffffffffu, idx >= 0 && (sval & PFLAG));
                int contrib;
                bool done;
                if (pm) {
                    int lp = __ffs(pm) - 1;       // closest predecessor with P
                    contrib = (lane <= lp) ? (sval & VMASK) : 0;
                    done = true;
                } else {
                    contrib = (idx >= 0) ? (sval & VMASK) : 0;
                    done = false;
                }
#pragma unroll
                for (int o = 16; o; o >>= 1)
                    contrib += __shfl_down_sync(0xffffffffu, contrib, o);
                if (lane == 0) run += contrib;
                if (done) break;
                j -= 32;
            }
            if (lane == 0) {
                s_prefix = run;
                atomicExch(&g_part[b], PFLAG | ((run + total) & VMASK));
            }
        }
    }
    __syncthreads();

    int incl = s_prefix + sh[t];
    int excl = incl - v;
    if (i < N_NODES) {
        g_rowptr[i + 1] = incl;
        g_col[excl] = i;          // self loop first in row
        g_fill[i] = excl + 1;
    }
    if (i == 0) g_rowptr[0] = 0;
}

// ---------------- scatter: 4 edges/thread ----------------
__global__ void scatter_kernel(const int* __restrict__ src,
                               const int* __restrict__ dst) {
    int e4 = blockIdx.x * blockDim.x + threadIdx.x;
    if (e4 < N_EDGES / 4) {
        int4 s = ((const int4*)src)[e4];
        int4 d = ((const int4*)dst)[e4];
        int p0 = atomicAdd(&g_fill[d.x], 1);
        int p1 = atomicAdd(&g_fill[d.y], 1);
        int p2 = atomicAdd(&g_fill[d.z], 1);
        int p3 = atomicAdd(&g_fill[d.w], 1);
        g_col[p0] = s.x;
        g_col[p1] = s.y;
        g_col[p2] = s.z;
        g_col[p3] = s.w;
    }
}

// ---------------- fp16 mma.sync GEMM, cp.async 4-stage, ldmatrix frags ------
// C[N_PAD, 512] = A[N_PAD, K] @ Wt^T   (Wt: [512][K] fp16, n-major)
// CTA tile 128x128, 8 warps (2m x 4n), warp tile 64x32, BK=32 (2 k16 steps).
#define GBM 128
#define GBN 128
#define GBK 32
#define PITCH 40                             // halfs per row
#define A_ST (GBM * PITCH)                   // 5120 halfs
#define B_ST (GBN * PITCH)                   // 5120 halfs
#define STAGE_HALFS (A_ST + B_ST)            // 10240 halfs (20 KB)
#define STG 4
#define GEMM_SMEM (STG * STAGE_HALFS * 2)    // 81920 bytes

__global__ __launch_bounds__(256, 2)
void gemm_f16_kernel(const __half* __restrict__ A,
                     const __half* __restrict__ Wt,
                     __half* __restrict__ Cout, int K) {
    extern __shared__ __half smh[];
    const uint32_t sbase = smem_u32(smh);

    int tid = threadIdx.x;
    int lane = tid & 31, wid = tid >> 5;
    int warp_m = wid >> 2;           // 0..1 (64 rows)
    int warp_n = wid & 3;            // 0..3 (32 cols)
    int fr = lane >> 2, fk = lane & 3;

    int row0 = blockIdx.y * GBM;
    int col0 = blockIdx.x * GBN;

    const int nch = K / GBK;

    // ldmatrix per-thread coordinates
    int aRow = warp_m * 64 + (lane & 15);
    int aColH = (lane >> 4) * 8;                               // halfs
    int bRow = warp_n * 32 + ((lane >> 4) * 8) + (lane & 7);
    int bColH = ((lane >> 3) & 1) * 8;                         // halfs

    auto issue = [&](int ch) {
        uint32_t sA = sbase + (uint32_t)(ch % STG) * (STAGE_HALFS * 2);
        uint32_t sB = sA + A_ST * 2;
        const __half* aG = A + (size_t)row0 * K + ch * GBK;
        const __half* bG = Wt + (size_t)col0 * K + ch * GBK;
#pragma unroll
        for (int i = 0; i < 2; i++) {
            int idx = tid + i * 256;          // 512 16B-chunks for A
            int m = idx >> 2, q = idx & 3;
            cp_async16(sA + (uint32_t)(m * PITCH + q * 8) * 2,
                       aG + (size_t)m * K + q * 8);
        }
#pragma unroll
        for (int i = 0; i < 2; i++) {
            int idx = tid + i * 256;          // 512 16B-chunks for B
            int n = idx >> 2, q = idx & 3;
            cp_async16(sB + (uint32_t)(n * PITCH + q * 8) * 2,
                       bG + (size_t)n * K + q * 8);
        }
        cp_commit();
    };

    for (int p = 0; p < STG - 1 && p < nch; p++) issue(p);

    float acc[4][4][4] = {};

    for (int ch = 0; ch < nch; ch++) {
        int rem = nch - 1 - ch;
        if (rem >= 2) cp_wait<2>(); else if (rem == 1) cp_wait<1>(); else cp_wait<0>();
        __syncthreads();
        if (ch + STG - 1 < nch) issue(ch + STG - 1);

        uint32_t stA = sbase + (uint32_t)(ch % STG) * (STAGE_HALFS * 2);
        uint32_t stB = stA + A_ST * 2;
#pragma unroll
        for (int ks = 0; ks < 2; ks++) {
            uint32_t af[4][4];
#pragma unroll
            for (int mt = 0; mt < 4; mt++) {
                uint32_t ad = stA + (uint32_t)((aRow + mt * 16) * PITCH + aColH + ks * 16) * 2;
                asm volatile(
                    "ldmatrix.sync.aligned.m8n8.x4.shared.b16 {%0,%1,%2,%3}, [%4];"
                    : "=r"(af[mt][0]), "=r"(af[mt][1]),
                      "=r"(af[mt][2]), "=r"(af[mt][3]) : "r"(ad));
            }
            uint32_t bf[4][2];
#pragma unroll
            for (int p = 0; p < 2; p++) {
                uint32_t bd = stB + (uint32_t)((bRow + p * 16) * PITCH + bColH + ks * 16) * 2;
                uint32_t r0, r1, r2, r3;
                asm volatile(
                    "ldmatrix.sync.aligned.m8n8.x4.shared.b16 {%0,%1,%2,%3}, [%4];"
                    : "=r"(r0), "=r"(r1), "=r"(r2), "=r"(r3) : "r"(bd));
                bf[2 * p][0] = r0; bf[2 * p][1] = r1;
                bf[2 * p + 1][0] = r2; bf[2 * p + 1][1] = r3;
            }
#pragma unroll
            for (int mt = 0; mt < 4; mt++)
#pragma unroll
                for (int nt = 0; nt < 4; nt++) {
                    float* c = acc[mt][nt];
                    asm volatile(
                        "mma.sync.aligned.m16n8k16.row.col.f32.f16.f16.f32 "
                        "{%0,%1,%2,%3}, {%4,%5,%6,%7}, {%8,%9}, {%0,%1,%2,%3};"
                        : "+f"(c[0]), "+f"(c[1]), "+f"(c[2]), "+f"(c[3])
                        : "r"(af[mt][0]), "r"(af[mt][1]), "r"(af[mt][2]),
                          "r"(af[mt][3]), "r"(bf[nt][0]), "r"(bf[nt][1]));
                }
        }
    }
    __syncthreads();

    // epilogue: fp32 acc -> half2 stores (rows padded: no guards)
#pragma unroll
    for (int mt = 0; mt < 4; mt++) {
#pragma unroll
        for (int nt = 0; nt < 4; nt++) {
            int row = row0 + warp_m * 64 + mt * 16 + fr;
            int col = col0 + warp_n * 32 + nt * 8 + 2 * fk;
            float* c = acc[mt][nt];
            *(__half2*)&Cout[(size_t)row * NLR + col] = __floats2half2_rn(c[0], c[1]);
            *(__half2*)&Cout[(size_t)(row + 8) * NLR + col] = __floats2half2_rn(c[2], c[3]);
        }
    }
}

// ---------------- fused GATv2 edge kernel (warp per node, online softmax) ----
__global__ void gat_edge_kernel(const __half* __restrict__ xlr,
                                const float* __restrict__ att,
                                const float* __restrict__ bias,
                                const __half* __restrict__ hprev,
                                __half* __restrict__ hout,
                                int residual) {
    int gw = (blockIdx.x * blockDim.x + threadIdx.x) >> 5;
    if (gw >= N_NODES) return;
    int lane = threadIdx.x & 31;
    int cbase = lane * 8;

    float xr_r[8], att_r[8];
    {
        uint4 u = *(const uint4*)&xlr[(size_t)gw * NLR + HC + cbase];
        const __half2* hp = (const __half2*)&u;
#pragma unroll
        for (int j = 0; j < 4; j++) {
            float2 f = __half22float2(hp[j]);
            xr_r[2 * j] = f.x; xr_r[2 * j + 1] = f.y;
        }
        const float4* q = (const float4*)&att[cbase];
        float4 c = q[0], d = q[1];
        att_r[0]=c.x; att_r[1]=c.y; att_r[2]=c.z; att_r[3]=c.w;
        att_r[4]=d.x; att_r[5]=d.y; att_r[6]=d.z; att_r[7]=d.w;
    }

    int e0 = g_rowptr[gw];
    int e1 = g_rowptr[gw + 1];

    float m = -INFINITY, den = 0.f;
    float acc[8] = {0.f,0.f,0.f,0.f,0.f,0.f,0.f,0.f};

    for (int base = e0; base < e1; base += 4) {
        int lim = e1 - base; if (lim > 4) lim = 4;
        int idx[4];
        uint4 u[4];
#pragma unroll
        for (int d = 0; d < 4; d++)
            if (d < lim) idx[d] = g_col[base + d];
#pragma unroll
        for (int d = 0; d < 4; d++)
            if (d < lim) u[d] = *(const uint4*)&xlr[(size_t)idx[d] * NLR + cbase];

#pragma unroll
        for (int d = 0; d < 4; d++) {
            if (d >= lim) break;
            const __half2* hp = (const __half2*)&u[d];
            float xv[8];
#pragma unroll
            for (int j = 0; j < 4; j++) {
                float2 f = __half22float2(hp[j]);
                xv[2 * j] = f.x; xv[2 * j + 1] = f.y;
            }

            float partial = 0.f;
#pragma unroll
            for (int j = 0; j < 8; j++) {
                float t = xv[j] + xr_r[j];
                t = fmaxf(t, NEG_SLOPE * t);      // leaky_relu
                partial = fmaf(t, att_r[j], partial);
            }
            partial += __shfl_xor_sync(0xffffffffu, partial, 1);
            partial += __shfl_xor_sync(0xffffffffu, partial, 2);
            partial += __shfl_xor_sync(0xffffffffu, partial, 4);
            float logit = partial;

            float m_new = fmaxf(m, logit);
            float scale = __expf(m - m_new);
            float pxe = __expf(logit - m_new);
            den = den * scale + pxe;
#pragma unroll
            for (int j = 0; j < 8; j++)
                acc[j] = fmaf(acc[j], scale, pxe * xv[j]);
            m = m_new;
        }
    }

    float inv = 1.f / (den + 1e-16f);
#pragma unroll
    for (int j = 0; j < 8; j++) {
        float v = fmaf(acc[j], inv, bias[cbase + j]);
        v = (v > 0.f) ? v : (__expf(v) - 1.f);            // ELU
        if (residual) v += __half2float(hprev[gw * HC + cbase + j]);
        hout[gw * HC + cbase + j] = __float2half(v);
    }
}

// ---------------- pooling: partial mean+max, then combine + head ----------------
__global__ void pool1_kernel(const __half* __restrict__ h) {
    int g = blockIdx.y, ch = blockIdx.x;       // 8 chunks of 125 nodes
    int c = threadIdx.x;                       // 256
    const __half* base = h + ((size_t)g * NODES_PG + ch * 125) * HC;
    float s = 0.f, mx = -INFINITY;
    for (int n = 0; n < 125; n++) {
        float v = __half2float(base[n * HC + c]);
        s += v;
        mx = fmaxf(mx, v);
    }
    float* out = &g_poolP[(size_t)(g * 8 + ch) * 2 * HC];
    out[c] = s;
    out[HC + c] = mx;
}

__global__ void pool2_head_kernel(const float* __restrict__ Wout,
                                  const float* __restrict__ bout,
                                  float* __restrict__ out) {
    __shared__ float xg[2 * HC];
    int g = blockIdx.x;
    int t = threadIdx.x;                       // 256
    float s = 0.f, mx = -INFINITY;
    for (int ch = 0; ch < 8; ch++) {
        const float* in = &g_poolP[(size_t)(g * 8 + ch) * 2 * HC];
        s += in[t];
        mx = fmaxf(mx, in[HC + t]);
    }
    xg[t] = s * (1.f / NODES_PG);
    xg[HC + t] = mx;
    __syncthreads();
    if (t < OUT_DIM) {
        float acc = bout[t];
#pragma unroll 8
        for (int k = 0; k < 2 * HC; k++)
            acc = fmaf(xg[k], Wout[k * OUT_DIM + t], acc);
        out[g * OUT_DIM + t] = acc;
    }
}

// ---------------- launch ----------------
extern "C" void kernel_launch(void* const* d_in, const int* in_sizes, int n_in,
                              void* d_out, int out_size) {
    const float* x    = (const float*)d_in[0];
    const int*   ei   = (const int*)d_in[1];     // [2, E] int32: row0 src, row1 dst
    const float* Win  = (const float*)d_in[3];
    const float* bin  = (const float*)d_in[4];
    const float* Wout = (const float*)d_in[5];
    const float* bout = (const float*)d_in[6];
    const float* Wl[3] = { (const float*)d_in[7],  (const float*)d_in[11], (const float*)d_in[15] };
    const float* Wr[3] = { (const float*)d_in[8],  (const float*)d_in[12], (const float*)d_in[16] };
    const float* At[3] = { (const float*)d_in[9],  (const float*)d_in[13], (const float*)d_in[17] };
    const float* Bi[3] = { (const float*)d_in[10], (const float*)d_in[14], (const float*)d_in[18] };
    float* out = (float*)d_out;

    const int* src = ei;
    const int* dst = ei + N_EDGES;

    __half *hA, *hB, *xlr, *Wt0, *Wt1, *Wt2;
    cudaGetSymbolAddress((void**)&hA,  g_hA);
    cudaGetSymbolAddress((void**)&hB,  g_hB);
    cudaGetSymbolAddress((void**)&xlr, g_xlr);
    cudaGetSymbolAddress((void**)&Wt0, g_Wt0);
    cudaGetSymbolAddress((void**)&Wt1, g_Wt1);
    cudaGetSymbolAddress((void**)&Wt2, g_Wt2);

    cudaFuncSetAttribute(gemm_f16_kernel,
                         cudaFuncAttributeMaxDynamicSharedMemorySize, GEMM_SMEM);

    // lazily-created side stream + fork/join events (host objects, reused)
    static cudaStream_t sB = nullptr;
    static cudaEvent_t evFork = nullptr, evJoin = nullptr;
    if (!sB) {
        cudaStreamCreateWithFlags(&sB, cudaStreamNonBlocking);
        cudaEventCreateWithFlags(&evFork, cudaEventDisableTiming);
        cudaEventCreateWithFlags(&evJoin, cudaEventDisableTiming);
    }

    // fork: CSR chain on side stream, overlapped with init + GEMM-0
    cudaEventRecord(evFork, 0);
    cudaStreamWaitEvent(sB, evFork, 0);
    initcnt_kernel<<<NBLK_SCAN, 256, 0, sB>>>();
    hist_kernel<<<(N_EDGES / 4 + 255) / 256, 256, 0, sB>>>(dst);
    scanfill_kernel<<<NBLK_SCAN, 256, 0, sB>>>();
    scatter_kernel<<<(N_EDGES / 4 + 255) / 256, 256, 0, sB>>>(src, dst);
    cudaEventRecord(evJoin, sB);

    // main stream: weight prep + input proj -> GEMM-0
    fused_init_kernel<<<INIT_BLOCKS, 256>>>(x, Win, bin,
                                            Wl[0], Wr[0], Wl[1], Wr[1], Wl[2], Wr[2]);

    dim3 ggrid(4, N_PAD / GBM);               // 4 N-tiles x 157 M-tiles
    const int EDGE_THREADS = 256;
    int edge_blocks = (N_NODES * 32 + EDGE_THREADS - 1) / EDGE_THREADS;

    gemm_f16_kernel<<<ggrid, 256, GEMM_SMEM>>>(hA, Wt0, xlr, C_DIM);

    // join: edge kernels need the CSR
    cudaStreamWaitEvent(0, evJoin, 0);

    // layer 0: no residual
    gat_edge_kernel<<<edge_blocks, EDGE_THREADS>>>(xlr, At[0], Bi[0], hA, hB, 0);

    // layer 1: in hB (K=256) -> out hA, residual hB
    gemm_f16_kernel<<<ggrid, 256, GEMM_SMEM>>>(hB, Wt1, xlr, HC);
    gat_edge_kernel<<<edge_blocks, EDGE_THREADS>>>(xlr, At[1], Bi[1], hB, hA, 1);

    // layer 2: in hA -> out hB, residual hA
    gemm_f16_kernel<<<ggrid, 256, GEMM_SMEM>>>(hA, Wt2, xlr, HC);
    gat_edge_kernel<<<edge_blocks, EDGE_THREADS>>>(xlr, At[2], Bi[2], hA, hB, 1);

    // pooling + head
    pool1_kernel<<<dim3(8, G_GRAPHS), HC>>>(hB);
    pool2_head_kernel<<<G_GRAPHS, HC>>>(Wout, bout, out);
}